// round 11
// baseline (speedup 1.0000x reference)
#include <cuda_runtime.h>
#include <cuda_fp16.h>
#include <math.h>
#include <stdint.h>

// Problem constants
#define BB   2
#define SS   1024
#define DD   768
#define HH   12
#define DHH  64
#define LL   6
#define FF   3072
#define RELV 32
#define NROW (BB*SS)          // 2048 token rows

// ---------------------------------------------------------------------------
// Scratch (device globals; no dynamic allocation allowed)
// ---------------------------------------------------------------------------
__device__ float g_x  [NROW*DD];
__device__ float g_h  [NROW*DD];
__device__ float g_q  [NROW*DD];
__device__ float g_k  [NROW*DD];
__device__ float g_v  [NROW*DD];
__device__ float g_ctx[NROW*DD];
__device__ float g_ffn[(size_t)NROW*FF];
__device__ uint8_t g_packed[(size_t)BB*SS*SS];   // rel_id | ((1-mask)<<5)

// ---------------------------------------------------------------------------
// fp16 helpers
// ---------------------------------------------------------------------------
__device__ __forceinline__ void h_split(float v, __half& hi, __half& lo) {
    hi = __float2half_rn(v);
    lo = __float2half_rn(v - __half2float(hi));
}

__device__ __forceinline__ uint32_t pack2(__half a, __half b) {
    __half2 t = __halves2half2(a, b);
    return *reinterpret_cast<uint32_t*>(&t);
}

__device__ __forceinline__ void mma_f16(float c[4], uint32_t a0, uint32_t a1,
                                        uint32_t a2, uint32_t a3,
                                        uint32_t b0, uint32_t b1) {
    asm volatile(
        "mma.sync.aligned.m16n8k16.row.col.f32.f16.f16.f32 "
        "{%0,%1,%2,%3},{%4,%5,%6,%7},{%8,%9},{%0,%1,%2,%3};"
        : "+f"(c[0]), "+f"(c[1]), "+f"(c[2]), "+f"(c[3])
        : "r"(a0), "r"(a1), "r"(a2), "r"(a3), "r"(b0), "r"(b1));
}

__device__ __forceinline__ void mma_f16a(float c[4], const uint32_t a[4],
                                         uint32_t b0, uint32_t b1) {
    mma_f16(c, a[0], a[1], a[2], a[3], b0, b1);
}

__device__ __forceinline__ void ldsm4(uint32_t& r0, uint32_t& r1,
                                      uint32_t& r2, uint32_t& r3, uint32_t a) {
    asm volatile("ldmatrix.sync.aligned.m8n8.x4.shared.b16 {%0,%1,%2,%3}, [%4];"
                 : "=r"(r0), "=r"(r1), "=r"(r2), "=r"(r3) : "r"(a));
}

__device__ __forceinline__ void ldsm4t(uint32_t& r0, uint32_t& r1,
                                       uint32_t& r2, uint32_t& r3, uint32_t a) {
    asm volatile("ldmatrix.sync.aligned.m8n8.x4.trans.shared.b16 {%0,%1,%2,%3}, [%4];"
                 : "=r"(r0), "=r"(r1), "=r"(r2), "=r"(r3) : "r"(a));
}

__device__ __forceinline__ float gelu_tanh(float v) {
    float u = 0.7978845608028654f * (v + 0.044715f * v * v * v);
    return 0.5f * v * (1.0f + tanhf(u));
}

// ---------------------------------------------------------------------------
// pack kernel: code = rel_id | ((1-mask)<<5), once per replay
// ---------------------------------------------------------------------------
__global__ void pack_kernel(const int* __restrict__ rel_ids,
                            const int* __restrict__ mask,
                            uint8_t* __restrict__ out, int n4)
{
    int i = blockIdx.x * 256 + threadIdx.x;
    if (i >= n4) return;
    int4 r = reinterpret_cast<const int4*>(rel_ids)[i];
    int4 m = reinterpret_cast<const int4*>(mask)[i];
    uchar4 o;
    o.x = (uint8_t)(r.x | ((1 - m.x) << 5));
    o.y = (uint8_t)(r.y | ((1 - m.y) << 5));
    o.z = (uint8_t)(r.z | ((1 - m.z) << 5));
    o.w = (uint8_t)(r.w | ((1 - m.w) << 5));
    reinterpret_cast<uchar4*>(out)[i] = o;
}

// ---------------------------------------------------------------------------
// Tensor-core GEMM core: fp16x3 split (C += Ah.Bh + Al.Bh + Ah.Bl) => ~fp32
// A fragments via ldmatrix.x4; B fragments via ldmatrix.x4.trans.
// EPI: 0=+bias, 1=+bias+gelu, 2=+bias+residual
// ---------------------------------------------------------------------------
template<int NT, int BM, int BN, int WM, int WN, int EPI>
__device__ __forceinline__ void gemm_core(
    const float* __restrict__ A, int lda,
    const float* __restrict__ B, int ldb,
    const float* __restrict__ bias,
    const float* __restrict__ R, int ldr,
    float* __restrict__ C, int ldc,
    int K, int m0, int n0)
{
    constexpr int NWN = BN / WN;
    constexpr int NMT = WM / 16;
    constexpr int NNT = WN / 8;
    constexpr int NA4 = (BM * 16) / (4 * NT);
    constexpr int NB4 = (BN * 16) / (4 * NT);
    constexpr int AKP = 24;
    constexpr int BNP = BN + 8;
    constexpr int ASZ = BM * AKP;
    constexpr int BSZ = 16 * BNP;

    __shared__ __align__(16) __half sh[2 * ASZ + 2 * BSZ];
    __half* Ah = sh;
    __half* Al = sh + ASZ;
    __half* Bh = sh + 2 * ASZ;
    __half* Bl = sh + 2 * ASZ + BSZ;

    const int tid  = threadIdx.x;
    const int lane = tid & 31;
    const int wid  = tid >> 5;
    const int g    = lane >> 2;
    const int t    = lane & 3;
    const int wm   = (wid / NWN) * WM;
    const int wn   = (wid % NWN) * WN;

    const int lk    = ((lane >> 3) & 1) * 8 + (lane & 7);
    const int lncol = ((lane >> 4) & 1) * 8;
    const int mi    = lane >> 3;
    const int mr    = lane & 7;
    const uint32_t ahb = (uint32_t)__cvta_generic_to_shared(Ah);
    const uint32_t alb = (uint32_t)__cvta_generic_to_shared(Al);
    const uint32_t bhb = (uint32_t)__cvta_generic_to_shared(Bh);
    const uint32_t blb = (uint32_t)__cvta_generic_to_shared(Bl);

    const float* Ap = A + (size_t)m0 * lda;
    const float* Bp = B + n0;

    float acc[NMT][NNT][4];
    #pragma unroll
    for (int i = 0; i < NMT; i++)
        #pragma unroll
        for (int j = 0; j < NNT; j++)
            #pragma unroll
            for (int e = 0; e < 4; e++) acc[i][j][e] = 0.f;

    float4 rA[NA4], rB[NB4];

    auto gload = [&](int k0) {
        #pragma unroll
        for (int e = 0; e < NA4; e++) {
            int f = tid + e * NT;
            rA[e] = *reinterpret_cast<const float4*>(
                Ap + (size_t)(f >> 2) * lda + k0 + (f & 3) * 4);
        }
        #pragma unroll
        for (int e = 0; e < NB4; e++) {
            int f = tid + e * NT;
            rB[e] = *reinterpret_cast<const float4*>(
                Bp + (size_t)(k0 + f / (BN / 4)) * ldb + (f % (BN / 4)) * 4);
        }
    };

    auto sstore = [&]() {
        #pragma unroll
        for (int e = 0; e < NA4; e++) {
            int f = tid + e * NT; int m = f >> 2; int kq = (f & 3) * 4;
            float vv[4] = {rA[e].x, rA[e].y, rA[e].z, rA[e].w};
            __half hh[4], ll[4];
            #pragma unroll
            for (int i = 0; i < 4; i++) h_split(vv[i], hh[i], ll[i]);
            uint2 ph, pl;
            ph.x = pack2(hh[0], hh[1]); ph.y = pack2(hh[2], hh[3]);
            pl.x = pack2(ll[0], ll[1]); pl.y = pack2(ll[2], ll[3]);
            *reinterpret_cast<uint2*>(Ah + m * AKP + kq) = ph;
            *reinterpret_cast<uint2*>(Al + m * AKP + kq) = pl;
        }
        #pragma unroll
        for (int e = 0; e < NB4; e++) {
            int f = tid + e * NT; int kk = f / (BN / 4); int nq = (f % (BN / 4)) * 4;
            float vv[4] = {rB[e].x, rB[e].y, rB[e].z, rB[e].w};
            __half hh[4], ll[4];
            #pragma unroll
            for (int i = 0; i < 4; i++) h_split(vv[i], hh[i], ll[i]);
            uint2 ph, pl;
            ph.x = pack2(hh[0], hh[1]); ph.y = pack2(hh[2], hh[3]);
            pl.x = pack2(ll[0], ll[1]); pl.y = pack2(ll[2], ll[3]);
            *reinterpret_cast<uint2*>(Bh + kk * BNP + nq) = ph;
            *reinterpret_cast<uint2*>(Bl + kk * BNP + nq) = pl;
        }
    };

    gload(0);
    sstore();
    __syncthreads();

    const int ntiles = K >> 4;
    for (int kt = 0; kt < ntiles; kt++) {
        const bool more = (kt + 1 < ntiles);
        if (more) gload((kt + 1) << 4);

        uint32_t ah[NMT][4], al[NMT][4];
        #pragma unroll
        for (int mt = 0; mt < NMT; mt++) {
            uint32_t aoff = (uint32_t)((wm + mt * 16 + (mi & 1) * 8 + mr) * AKP
                                       + (mi >> 1) * 8) * 2;
            ldsm4(ah[mt][0], ah[mt][1], ah[mt][2], ah[mt][3], ahb + aoff);
            ldsm4(al[mt][0], al[mt][1], al[mt][2], al[mt][3], alb + aoff);
        }

        #pragma unroll
        for (int np = 0; np < NNT / 2; np++) {
            uint32_t off = (uint32_t)(lk * BNP + wn + np * 16 + lncol) * 2;
            uint32_t b0, b1, b2, b3, c0, c1, c2, c3;
            ldsm4t(b0, b1, b2, b3, bhb + off);
            ldsm4t(c0, c1, c2, c3, blb + off);
            #pragma unroll
            for (int mt = 0; mt < NMT; mt++) {
                mma_f16a(acc[mt][2 * np],     ah[mt], b0, b1);
                mma_f16a(acc[mt][2 * np],     al[mt], b0, b1);
                mma_f16a(acc[mt][2 * np],     ah[mt], c0, c1);
                mma_f16a(acc[mt][2 * np + 1], ah[mt], b2, b3);
                mma_f16a(acc[mt][2 * np + 1], al[mt], b2, b3);
                mma_f16a(acc[mt][2 * np + 1], ah[mt], c2, c3);
            }
        }
        __syncthreads();
        if (more) { sstore(); __syncthreads(); }
    }

    // Epilogue
    #pragma unroll
    for (int mt = 0; mt < NMT; mt++) {
        int r0 = m0 + wm + mt * 16 + g;
        #pragma unroll
        for (int nt = 0; nt < NNT; nt++) {
            int cc = n0 + wn + nt * 8 + t * 2;
            float2 p0 = make_float2(acc[mt][nt][0], acc[mt][nt][1]);
            float2 p1 = make_float2(acc[mt][nt][2], acc[mt][nt][3]);
            float b0 = bias[cc], b1 = bias[cc + 1];
            p0.x += b0; p0.y += b1; p1.x += b0; p1.y += b1;
            if (EPI == 1) {
                p0.x = gelu_tanh(p0.x); p0.y = gelu_tanh(p0.y);
                p1.x = gelu_tanh(p1.x); p1.y = gelu_tanh(p1.y);
            }
            if (EPI == 2) {
                p0.x += R[(size_t)r0 * ldr + cc];
                p0.y += R[(size_t)r0 * ldr + cc + 1];
                p1.x += R[(size_t)(r0 + 8) * ldr + cc];
                p1.y += R[(size_t)(r0 + 8) * ldr + cc + 1];
            }
            *reinterpret_cast<float2*>(&C[(size_t)r0 * ldc + cc]) = p0;
            *reinterpret_cast<float2*>(&C[(size_t)(r0 + 8) * ldc + cc]) = p1;
        }
    }
}

// QKV fused via blockIdx.z — 512 threads
__global__ __launch_bounds__(512, 1)
void qkv_kernel(const float* __restrict__ h,
                const float* __restrict__ wq, const float* __restrict__ wk,
                const float* __restrict__ wv,
                const float* __restrict__ bq, const float* __restrict__ bk,
                const float* __restrict__ bv,
                float* __restrict__ q, float* __restrict__ k, float* __restrict__ v)
{
    int z = blockIdx.z;
    const float* W  = (z == 0) ? wq : (z == 1) ? wk : wv;
    const float* bi = (z == 0) ? bq : (z == 1) ? bk : bv;
    float* C        = (z == 0) ? q  : (z == 1) ? k  : v;
    gemm_core<512,128,128,32,32,0>(h, DD, W, DD, bi, nullptr, 0, C, DD,
                                   DD, blockIdx.y * 128, blockIdx.x * 128);
}

// FFN1 — 512 threads
__global__ __launch_bounds__(512, 1)
void ffn1_kernel(const float* __restrict__ A,
                 const float* __restrict__ B,
                 const float* __restrict__ bias,
                 float* __restrict__ C)
{
    gemm_core<512,128,128,32,32,1>(A, DD, B, FF, bias, nullptr, 0, C, FF,
                                   DD, blockIdx.y * 128, blockIdx.x * 128);
}

// O-proj / FFN2 — 256 threads, occ 2
template<int EPI>
__global__ __launch_bounds__(256, 2)
void mm_kernel(const float* __restrict__ A, int lda,
               const float* __restrict__ B, int ldb,
               const float* __restrict__ bias,
               const float* __restrict__ R, int ldr,
               float* __restrict__ C, int ldc, int K)
{
    gemm_core<256,64,128,32,32,EPI>(A, lda, B, ldb, bias, R, ldr, C, ldc,
                                    K, blockIdx.y * 64, blockIdx.x * 128);
}

// ---------------------------------------------------------------------------
// Fused flash attention + in-kernel rel bias. BJ=64 j-tiles (16 iters).
// K & V fragments via ldmatrix.x4; packed uint8 rel/mask gather. occ 3.
// ---------------------------------------------------------------------------
__global__ __launch_bounds__(128, 3)
void flash_kernel(const float* __restrict__ q, const float* __restrict__ k,
                  const float* __restrict__ v, const float* __restrict__ relw,
                  const uint8_t* __restrict__ packed,
                  float* __restrict__ ctx)
{
    extern __shared__ float smf[];
    __half*  smh = reinterpret_cast<__half*>(smf);
    __half*  Qh = smh;                 // [64][72]
    __half*  Ql = smh + 4608;
    __half*  Kh = smh + 9216;          // [64][72]
    __half*  Kl = smh + 13824;
    __half*  Vt = smh + 18432;         // [64][72] plain fp16
    float*   rels = reinterpret_cast<float*>(smh + 23040);  // [64][33] fp32
    __half*  Rwh = smh + 27264;        // [32][72]
    __half*  Rwl = smh + 29568;        // [32][72]

    const int tid  = threadIdx.x;
    const int lane = tid & 31;
    const int wid  = tid >> 5;
    const int g = lane >> 2, t = lane & 3;
    const int wm = wid << 4;
    const int mi = lane >> 3, mr = lane & 7;
    const int lk    = ((lane >> 3) & 1) * 8 + (lane & 7);
    const int lncol = ((lane >> 4) & 1) * 8;

    const int i0 = blockIdx.x * 64;
    const int bh = blockIdx.y;
    const int b = bh / HH, h = bh - b * HH;

    const float* Qp = q + (size_t)b * SS * DD + h * DHH;
    const float* Kp = k + (size_t)b * SS * DD + h * DHH;
    const float* Vp = v + (size_t)b * SS * DD + h * DHH;

    const uint32_t qhb = (uint32_t)__cvta_generic_to_shared(Qh);
    const uint32_t qlb = (uint32_t)__cvta_generic_to_shared(Ql);
    const uint32_t khb = (uint32_t)__cvta_generic_to_shared(Kh);
    const uint32_t klb = (uint32_t)__cvta_generic_to_shared(Kl);
    const uint32_t vtb = (uint32_t)__cvta_generic_to_shared(Vt);
    const uint32_t rhb = (uint32_t)__cvta_generic_to_shared(Rwh);
    const uint32_t rlb = (uint32_t)__cvta_generic_to_shared(Rwl);

    // Q tile -> Qh/Ql [row][d]
    {
        int row = tid & 63;
        int base = (tid >> 6) * 8;
        #pragma unroll
        for (int e = 0; e < 8; e++) {
            int dq = (base + e) * 4;
            float4 val = *reinterpret_cast<const float4*>(Qp + (size_t)(i0 + row) * DD + dq);
            float vv[4] = {val.x, val.y, val.z, val.w};
            __half hh[4], ll[4];
            #pragma unroll
            for (int i = 0; i < 4; i++) h_split(vv[i], hh[i], ll[i]);
            uint2 ph, pl;
            ph.x = pack2(hh[0], hh[1]); ph.y = pack2(hh[2], hh[3]);
            pl.x = pack2(ll[0], ll[1]); pl.y = pack2(ll[2], ll[3]);
            *reinterpret_cast<uint2*>(Qh + row * 72 + dq) = ph;
            *reinterpret_cast<uint2*>(Ql + row * 72 + dq) = pl;
        }
    }
    // rel_emb slice [RELV][DHH] for head h -> Rwh/Rwl
    {
        #pragma unroll
        for (int e = 0; e < 4; e++) {
            int f = tid + e * 128;
            int r = f >> 4, dq = (f & 15) * 4;
            float4 val = *reinterpret_cast<const float4*>(
                relw + ((size_t)r * HH + h) * DHH + dq);
            float vv[4] = {val.x, val.y, val.z, val.w};
            __half hh[4], ll[4];
            #pragma unroll
            for (int i = 0; i < 4; i++) h_split(vv[i], hh[i], ll[i]);
            uint2 ph, pl;
            ph.x = pack2(hh[0], hh[1]); ph.y = pack2(hh[2], hh[3]);
            pl.x = pack2(ll[0], ll[1]); pl.y = pack2(ll[2], ll[3]);
            *reinterpret_cast<uint2*>(Rwh + r * 72 + dq) = ph;
            *reinterpret_cast<uint2*>(Rwl + r * 72 + dq) = pl;
        }
    }
    __syncthreads();

    // Hoisted Q fragments via ldmatrix (4 k16 chunks)
    uint32_t qfh[4][4], qfl[4][4];
    {
        uint32_t qoff = (uint32_t)((wm + (mi & 1) * 8 + mr) * 72 + (mi >> 1) * 8) * 2;
        #pragma unroll
        for (int kc = 0; kc < 4; kc++) {
            ldsm4(qfh[kc][0], qfh[kc][1], qfh[kc][2], qfh[kc][3], qhb + qoff + kc * 32);
            ldsm4(qfl[kc][0], qfl[kc][1], qfl[kc][2], qfl[kc][3], qlb + qoff + kc * 32);
        }
    }

    // In-kernel rel bias: rel[i][r] = Q @ Rw^T (fp16x3) -> rels smem
    {
        float racc[4][4];
        #pragma unroll
        for (int nt = 0; nt < 4; nt++) {
            racc[nt][0] = 0.f; racc[nt][1] = 0.f; racc[nt][2] = 0.f; racc[nt][3] = 0.f;
        }
        uint32_t kfix = (uint32_t)(((mi >> 1) * 8 + mr) * 72 + (mi & 1) * 8) * 2;
        #pragma unroll
        for (int np = 0; np < 2; np++) {
            #pragma unroll
            for (int kc = 0; kc < 4; kc++) {
                uint32_t off = kfix + (uint32_t)(np * 16 * 72 + kc * 16) * 2;
                uint32_t b0, b1, b2, b3, c0, c1, c2, c3;
                ldsm4(b0, b1, b2, b3, rhb + off);
                ldsm4(c0, c1, c2, c3, rlb + off);
                mma_f16a(racc[2 * np],     qfh[kc], b0, b1);
                mma_f16a(racc[2 * np],     qfl[kc], b0, b1);
                mma_f16a(racc[2 * np],     qfh[kc], c0, c1);
                mma_f16a(racc[2 * np + 1], qfh[kc], b2, b3);
                mma_f16a(racc[2 * np + 1], qfl[kc], b2, b3);
                mma_f16a(racc[2 * np + 1], qfh[kc], c2, c3);
            }
        }
        int r0 = wm + g, r1 = r0 + 8;
        #pragma unroll
        for (int nt = 0; nt < 4; nt++) {
            rels[r0 * 33 + nt * 8 + 2 * t]     = racc[nt][0];
            rels[r0 * 33 + nt * 8 + 2 * t + 1] = racc[nt][1];
            rels[r1 * 33 + nt * 8 + 2 * t]     = racc[nt][2];
            rels[r1 * 33 + nt * 8 + 2 * t + 1] = racc[nt][3];
        }
        __syncwarp();
    }

    float m0r = -1e30f, m1r = -1e30f;
    float l0r = 0.f, l1r = 0.f;
    float oacc[8][4];
    #pragma unroll
    for (int nt = 0; nt < 8; nt++) {
        oacc[nt][0] = 0.f; oacc[nt][1] = 0.f; oacc[nt][2] = 0.f; oacc[nt][3] = 0.f;
    }

    const int ig0 = i0 + wm + g;
    const int ig1 = ig0 + 8;
    const uint8_t* pk0 = packed + ((size_t)b * SS + ig0) * SS + 2 * t;
    const uint8_t* pk1 = packed + ((size_t)b * SS + ig1) * SS + 2 * t;
    const float* rl0 = rels + (wm + g) * 33;
    const float* rl1 = rl0 + 8 * 33;

    const uint32_t kfix = (uint32_t)(((mi >> 1) * 8 + mr) * 72 + (mi & 1) * 8) * 2;

    for (int jt = 0; jt < 16; jt++) {
        const int j0 = jt * 64;
        __syncthreads();
        // K tile -> Kh/Kl [j][d], 64 rows; V tile -> Vt [j][d] fp16
        {
            int row = tid >> 1;
            int base = (tid & 1) * 32;
            #pragma unroll
            for (int e = 0; e < 8; e++) {
                int dq = base + e * 4;
                float4 val = *reinterpret_cast<const float4*>(Kp + (size_t)(j0 + row) * DD + dq);
                float vv[4] = {val.x, val.y, val.z, val.w};
                __half hh[4], ll[4];
                #pragma unroll
                for (int i = 0; i < 4; i++) h_split(vv[i], hh[i], ll[i]);
                uint2 ph, pl;
                ph.x = pack2(hh[0], hh[1]); ph.y = pack2(hh[2], hh[3]);
                pl.x = pack2(ll[0], ll[1]); pl.y = pack2(ll[2], ll[3]);
                *reinterpret_cast<uint2*>(Kh + row * 72 + dq) = ph;
                *reinterpret_cast<uint2*>(Kl + row * 72 + dq) = pl;
            }
            #pragma unroll
            for (int e = 0; e < 8; e++) {
                int dq = base + e * 4;
                float4 val = *reinterpret_cast<const float4*>(Vp + (size_t)(j0 + row) * DD + dq);
                uint2 pv;
                pv.x = pack2(__float2half_rn(val.x), __float2half_rn(val.y));
                pv.y = pack2(__float2half_rn(val.z), __float2half_rn(val.w));
                *reinterpret_cast<uint2*>(Vt + row * 72 + dq) = pv;
            }
        }
        __syncthreads();

        // S = Q K^T, 8 n8-tiles per warp, K frags via ldmatrix.x4
        float sacc[8][4];
        #pragma unroll
        for (int nt = 0; nt < 8; nt++) {
            sacc[nt][0] = 0.f; sacc[nt][1] = 0.f; sacc[nt][2] = 0.f; sacc[nt][3] = 0.f;
        }
        #pragma unroll
        for (int np = 0; np < 4; np++) {
            #pragma unroll
            for (int kc = 0; kc < 4; kc++) {
                uint32_t off = kfix + (uint32_t)(np * 16 * 72 + kc * 16) * 2;
                uint32_t b0, b1, b2, b3, c0, c1, c2, c3;
                ldsm4(b0, b1, b2, b3, khb + off);
                ldsm4(c0, c1, c2, c3, klb + off);
                mma_f16a(sacc[2 * np],     qfh[kc], b0, b1);
                mma_f16a(sacc[2 * np],     qfl[kc], b0, b1);
                mma_f16a(sacc[2 * np],     qfh[kc], c0, c1);
                mma_f16a(sacc[2 * np + 1], qfh[kc], b2, b3);
                mma_f16a(sacc[2 * np + 1], qfl[kc], b2, b3);
                mma_f16a(sacc[2 * np + 1], qfh[kc], c2, c3);
            }
        }

        // packed rel/mask gather + scale
        float mx0 = -1e30f, mx1 = -1e30f;
        #pragma unroll
        for (int nt = 0; nt < 8; nt++) {
            int jo = j0 + nt * 8;
            uchar2 c0 = *reinterpret_cast<const uchar2*>(pk0 + jo);
            uchar2 c1 = *reinterpret_cast<const uchar2*>(pk1 + jo);
            sacc[nt][0] = (sacc[nt][0] + rl0[c0.x & 31]) * 0.125f - (float)(c0.x >> 5) * 10000.f;
            sacc[nt][1] = (sacc[nt][1] + rl0[c0.y & 31]) * 0.125f - (float)(c0.y >> 5) * 10000.f;
            sacc[nt][2] = (sacc[nt][2] + rl1[c1.x & 31]) * 0.125f - (float)(c1.x >> 5) * 10000.f;
            sacc[nt][3] = (sacc[nt][3] + rl1[c1.y & 31]) * 0.125f - (float)(c1.y >> 5) * 10000.f;
            mx0 = fmaxf(mx0, fmaxf(sacc[nt][0], sacc[nt][1]));
            mx1 = fmaxf(mx1, fmaxf(sacc[nt][2], sacc[nt][3]));
        }
        mx0 = fmaxf(mx0, __shfl_xor_sync(0xffffffffu, mx0, 1));
        mx0 = fmaxf(mx0, __shfl_xor_sync(0xffffffffu, mx0, 2));
        mx1 = fmaxf(mx1, __shfl_xor_sync(0xffffffffu, mx1, 1));
        mx1 = fmaxf(mx1, __shfl_xor_sync(0xffffffffu, mx1, 2));
        float mn0 = fmaxf(m0r, mx0), mn1 = fmaxf(m1r, mx1);
        float al0 = __expf(m0r - mn0), al1 = __expf(m1r - mn1);
        m0r = mn0; m1r = mn1;

        // p = exp(s - m), pack to half2 (A-fragment layout = C-fragment layout)
        uint32_t ph[8][2];
        float s0 = 0.f, s1 = 0.f;
        #pragma unroll
        for (int nt = 0; nt < 8; nt++) {
            float p0 = __expf(sacc[nt][0] - mn0);
            float p1 = __expf(sacc[nt][1] - mn0);
            float p2 = __expf(sacc[nt][2] - mn1);
            float p3 = __expf(sacc[nt][3] - mn1);
            s0 += p0 + p1; s1 += p2 + p3;
            __half2 h01 = __floats2half2_rn(p0, p1);
            __half2 h23 = __floats2half2_rn(p2, p3);
            ph[nt][0] = *reinterpret_cast<uint32_t*>(&h01);
            ph[nt][1] = *reinterpret_cast<uint32_t*>(&h23);
        }
        l0r = l0r * al0 + s0;
        l1r = l1r * al1 + s1;
        #pragma unroll
        for (int nt = 0; nt < 8; nt++) {
            oacc[nt][0] *= al0; oacc[nt][1] *= al0;
            oacc[nt][2] *= al1; oacc[nt][3] *= al1;
        }
        // O += P @ V  (fp16, K=64 in 4 chunks of 16), V frags via ldmatrix.x4.trans
        #pragma unroll
        for (int kc = 0; kc < 4; kc++) {
            uint32_t a0 = ph[2 * kc][0],     a1 = ph[2 * kc][1];
            uint32_t a2 = ph[2 * kc + 1][0], a3 = ph[2 * kc + 1][1];
            #pragma unroll
            for (int ntp = 0; ntp < 4; ntp++) {
                uint32_t off = (uint32_t)((kc * 16 + lk) * 72 + ntp * 16 + lncol) * 2;
                uint32_t b0, b1, b2, b3;
                ldsm4t(b0, b1, b2, b3, vtb + off);
                mma_f16(oacc[2 * ntp],     a0, a1, a2, a3, b0, b1);
                mma_f16(oacc[2 * ntp + 1], a0, a1, a2, a3, b2, b3);
            }
        }
    }

    // finalize
    l0r += __shfl_xor_sync(0xffffffffu, l0r, 1);
    l0r += __shfl_xor_sync(0xffffffffu, l0r, 2);
    l1r += __shfl_xor_sync(0xffffffffu, l1r, 1);
    l1r += __shfl_xor_sync(0xffffffffu, l1r, 2);
    float inv0 = 1.f / l0r, inv1 = 1.f / l1r;
    float* C0 = ctx + ((size_t)b * SS + ig0) * DD + h * DHH + 2 * t;
    float* C1 = ctx + ((size_t)b * SS + ig1) * DD + h * DHH + 2 * t;
    #pragma unroll
    for (int nt = 0; nt < 8; nt++) {
        *reinterpret_cast<float2*>(C0 + nt * 8) = make_float2(oacc[nt][0] * inv0, oacc[nt][1] * inv0);
        *reinterpret_cast<float2*>(C1 + nt * 8) = make_float2(oacc[nt][2] * inv1, oacc[nt][3] * inv1);
    }
}

// ---------------------------------------------------------------------------
// Block reduction (256 threads)
// ---------------------------------------------------------------------------
__device__ __forceinline__ float bsum256(float v) {
    __shared__ float sm[8];
    #pragma unroll
    for (int o = 16; o; o >>= 1) v += __shfl_xor_sync(0xffffffffu, v, o);
    if ((threadIdx.x & 31) == 0) sm[threadIdx.x >> 5] = v;
    __syncthreads();
    float r = 0.f;
    #pragma unroll
    for (int i = 0; i < 8; i++) r += sm[i];
    __syncthreads();
    return r;
}

// ---------------------------------------------------------------------------
// Embedding
// ---------------------------------------------------------------------------
__global__ void embed_kernel(const int* __restrict__ token_ids,
                             const int* __restrict__ segment_ids,
                             const int* __restrict__ position_ids,
                             const int* __restrict__ question_mask,
                             const float* __restrict__ tok_emb,
                             const float* __restrict__ seg_emb,
                             float* __restrict__ x)
{
    int row = blockIdx.x;
    int tok = token_ids[row];
    int seg = segment_ids[row];
    int qmi = question_mask[row];
    float qm = (float)qmi;
    int pos = position_ids[row] * qmi;
    float fpos = (float)pos;

    const float* te = tok_emb + (size_t)tok * DD;
    const float* se = seg_emb + (size_t)seg * DD;
    float* xr = x + (size_t)row * DD;

    for (int i = threadIdx.x; i < DD; i += 256) {
        float ex  = (float)(2 * (i >> 1)) * (1.0f / (float)DD);
        float inv = __powf(10000.0f, -ex);
        float ang = fpos * inv;
        float pe  = (i & 1) ? cosf(ang) : sinf(ang);
        xr[i] = te[i] + se[i] + pe * qm;
    }
}

// ---------------------------------------------------------------------------
// LayerNorm
// ---------------------------------------------------------------------------
__global__ void ln_kernel(const float* __restrict__ x,
                          const float* __restrict__ gamma,
                          const float* __restrict__ beta,
                          float* __restrict__ out)
{
    int row = blockIdx.x;
    const float* xr = x + (size_t)row * DD;
    int t = threadIdx.x;
    float v0 = xr[t], v1 = xr[t + 256], v2 = xr[t + 512];

    float s = bsum256(v0 + v1 + v2);
    float mu = s * (1.0f / (float)DD);
    float d0 = v0 - mu, d1 = v1 - mu, d2 = v2 - mu;
    float s2 = bsum256(d0*d0 + d1*d1 + d2*d2);
    float var = s2 * (1.0f / (float)DD);
    float rstd = rsqrtf(var + 1e-12f);

    float* orow = out + (size_t)row * DD;
    orow[t]       = d0 * rstd * gamma[t]       + beta[t];
    orow[t + 256] = d1 * rstd * gamma[t + 256] + beta[t + 256];
    orow[t + 512] = d2 * rstd * gamma[t + 512] + beta[t + 512];
}

// ---------------------------------------------------------------------------
// Launch
// ---------------------------------------------------------------------------
extern "C" void kernel_launch(void* const* d_in, const int* in_sizes, int n_in,
                              void* d_out, int out_size)
{
    const int* token_ids     = (const int*)d_in[0];
    const int* segment_ids   = (const int*)d_in[1];
    const int* position_ids  = (const int*)d_in[2];
    const int* question_mask = (const int*)d_in[3];
    const int* attention_mask= (const int*)d_in[4];
    const int* rel_ids       = (const int*)d_in[5];
    const float* tok_emb = (const float*)d_in[6];
    const float* seg_emb = (const float*)d_in[7];
    const float* ln1_g = (const float*)d_in[8];
    const float* ln1_b = (const float*)d_in[9];
    const float* ln2_g = (const float*)d_in[10];
    const float* ln2_b = (const float*)d_in[11];
    const float* wq = (const float*)d_in[12];
    const float* bq = (const float*)d_in[13];
    const float* wk = (const float*)d_in[14];
    const float* bk = (const float*)d_in[15];
    const float* wv = (const float*)d_in[16];
    const float* bv = (const float*)d_in[17];
    const float* wo = (const float*)d_in[18];
    const float* bo = (const float*)d_in[19];
    const float* rel_emb = (const float*)d_in[20];
    const float* w1 = (const float*)d_in[21];
    const float* b1 = (const float*)d_in[22];
    const float* w2 = (const float*)d_in[23];
    const float* b2 = (const float*)d_in[24];

    float *x, *h, *q, *k, *v, *ctx, *ff;
    uint8_t* packed;
    cudaGetSymbolAddress((void**)&x,   g_x);
    cudaGetSymbolAddress((void**)&h,   g_h);
    cudaGetSymbolAddress((void**)&q,   g_q);
    cudaGetSymbolAddress((void**)&k,   g_k);
    cudaGetSymbolAddress((void**)&v,   g_v);
    cudaGetSymbolAddress((void**)&ctx, g_ctx);
    cudaGetSymbolAddress((void**)&ff,  g_ffn);
    cudaGetSymbolAddress((void**)&packed, g_packed);

    const int FLASH_SMEM = 63744;
    cudaFuncSetAttribute(flash_kernel,
                         cudaFuncAttributeMaxDynamicSharedMemorySize, FLASH_SMEM);

    // Pack rel_ids + mask once (layer-invariant)
    {
        int n4 = (BB * SS * SS) / 4;
        pack_kernel<<<(n4 + 255) / 256, 256>>>(rel_ids, attention_mask, packed, n4);
    }

    embed_kernel<<<NROW, 256>>>(token_ids, segment_ids, position_ids,
                                question_mask, tok_emb, seg_emb, x);

    for (int l = 0; l < LL; l++) {
        const float* wq_l = wq + (size_t)l * DD * DD;
        const float* wk_l = wk + (size_t)l * DD * DD;
        const float* wv_l = wv + (size_t)l * DD * DD;
        const float* wo_l = wo + (size_t)l * DD * DD;
        const float* w1_l = w1 + (size_t)l * DD * FF;
        const float* w2_l = w2 + (size_t)l * FF * DD;

        // --- attention block ---
        ln_kernel<<<NROW, 256>>>(x, ln1_g + l * DD, ln1_b + l * DD, h);

        qkv_kernel<<<dim3(DD / 128, NROW / 128, 3), 512>>>(
            h, wq_l, wk_l, wv_l, bq + l * DD, bk + l * DD, bv + l * DD, q, k, v);

        flash_kernel<<<dim3(SS / 64, BB * HH), 128, FLASH_SMEM>>>(
            q, k, v, rel_emb + (size_t)l * RELV * HH * DHH, packed, ctx);

        // O-proj: BM=64, BN=128 -> grid (6,32)=192 CTAs, occ 2
        mm_kernel<2><<<dim3(DD / 128, NROW / 64), 256>>>(
            ctx, DD, wo_l, DD, bo + l * DD, x, DD, x, DD, DD);

        // --- FFN block ---
        ln_kernel<<<NROW, 256>>>(x, ln2_g + l * DD, ln2_b + l * DD, h);
        ffn1_kernel<<<dim3(FF / 128, NROW / 128), 512>>>(
            h, w1_l, b1 + l * FF, ff);

        float* outp = (l == LL - 1) ? (float*)d_out : x;
        // FFN2: BM=64, BN=128 -> grid (6,32)=192 CTAs, occ 2
        mm_kernel<2><<<dim3(DD / 128, NROW / 64), 256>>>(
            ff, FF, w2_l, DD, b2 + l * DD, x, DD, outp, DD, FF);
    }
}

// round 12
// speedup vs baseline: 1.0541x; 1.0541x over previous
#include <cuda_runtime.h>
#include <cuda_fp16.h>
#include <math.h>
#include <stdint.h>

// Problem constants
#define BB   2
#define SS   1024
#define DD   768
#define HH   12
#define DHH  64
#define LL   6
#define FF   3072
#define RELV 32
#define NROW (BB*SS)          // 2048 token rows

// ---------------------------------------------------------------------------
// Scratch (device globals; no dynamic allocation allowed)
// ---------------------------------------------------------------------------
__device__ float g_x  [NROW*DD];
__device__ float g_h  [NROW*DD];
__device__ float g_q  [NROW*DD];
__device__ float g_k  [NROW*DD];
__device__ float g_v  [NROW*DD];
__device__ float g_ctx[NROW*DD];
__device__ float g_ffn[(size_t)NROW*FF];

// ---------------------------------------------------------------------------
// fp16 helpers
// ---------------------------------------------------------------------------
__device__ __forceinline__ void h_split(float v, __half& hi, __half& lo) {
    hi = __float2half_rn(v);
    lo = __float2half_rn(v - __half2float(hi));
}

__device__ __forceinline__ uint32_t pack2(__half a, __half b) {
    __half2 t = __halves2half2(a, b);
    return *reinterpret_cast<uint32_t*>(&t);
}

__device__ __forceinline__ void mma_f16(float c[4], uint32_t a0, uint32_t a1,
                                        uint32_t a2, uint32_t a3,
                                        uint32_t b0, uint32_t b1) {
    asm volatile(
        "mma.sync.aligned.m16n8k16.row.col.f32.f16.f16.f32 "
        "{%0,%1,%2,%3},{%4,%5,%6,%7},{%8,%9},{%0,%1,%2,%3};"
        : "+f"(c[0]), "+f"(c[1]), "+f"(c[2]), "+f"(c[3])
        : "r"(a0), "r"(a1), "r"(a2), "r"(a3), "r"(b0), "r"(b1));
}

__device__ __forceinline__ void mma_f16a(float c[4], const uint32_t a[4],
                                         uint32_t b0, uint32_t b1) {
    mma_f16(c, a[0], a[1], a[2], a[3], b0, b1);
}

__device__ __forceinline__ void ldsm4(uint32_t& r0, uint32_t& r1,
                                      uint32_t& r2, uint32_t& r3, uint32_t a) {
    asm volatile("ldmatrix.sync.aligned.m8n8.x4.shared.b16 {%0,%1,%2,%3}, [%4];"
                 : "=r"(r0), "=r"(r1), "=r"(r2), "=r"(r3) : "r"(a));
}

__device__ __forceinline__ void ldsm4t(uint32_t& r0, uint32_t& r1,
                                       uint32_t& r2, uint32_t& r3, uint32_t a) {
    asm volatile("ldmatrix.sync.aligned.m8n8.x4.trans.shared.b16 {%0,%1,%2,%3}, [%4];"
                 : "=r"(r0), "=r"(r1), "=r"(r2), "=r"(r3) : "r"(a));
}

__device__ __forceinline__ float gelu_tanh(float v) {
    float u = 0.7978845608028654f * (v + 0.044715f * v * v * v);
    return 0.5f * v * (1.0f + tanhf(u));
}

// ---------------------------------------------------------------------------
// Tensor-core GEMM core: fp16x3 split, DOUBLE-BUFFERED smem (1 sync/k-tile).
// A fragments via ldmatrix.x4; B fragments via ldmatrix.x4.trans.
// EPI: 0=+bias, 1=+bias+gelu, 2=+bias+residual
// ---------------------------------------------------------------------------
template<int NT, int BM, int BN, int WM, int WN, int EPI>
__device__ __forceinline__ void gemm_core(
    const float* __restrict__ A, int lda,
    const float* __restrict__ B, int ldb,
    const float* __restrict__ bias,
    const float* __restrict__ R, int ldr,
    float* __restrict__ C, int ldc,
    int K, int m0, int n0)
{
    constexpr int NWN = BN / WN;
    constexpr int NMT = WM / 16;
    constexpr int NNT = WN / 8;
    constexpr int NA4 = (BM * 16) / (4 * NT);
    constexpr int NB4 = (BN * 16) / (4 * NT);
    constexpr int AKP = 24;              // halfs per A row (16 + 8 pad)
    constexpr int BNP = BN + 8;          // halfs per B row
    constexpr int ASZ = BM * AKP;
    constexpr int BSZ = 16 * BNP;
    constexpr int STG = 2 * ASZ + 2 * BSZ;   // halfs per stage

    __shared__ __align__(16) __half sh[2 * STG];

    const int tid  = threadIdx.x;
    const int lane = tid & 31;
    const int wid  = tid >> 5;
    const int g    = lane >> 2;
    const int t    = lane & 3;
    const int wm   = (wid / NWN) * WM;
    const int wn   = (wid % NWN) * WN;

    const int lk    = ((lane >> 3) & 1) * 8 + (lane & 7);
    const int lncol = ((lane >> 4) & 1) * 8;
    const int mi    = lane >> 3;
    const int mr    = lane & 7;
    const uint32_t shb = (uint32_t)__cvta_generic_to_shared(sh);

    const float* Ap = A + (size_t)m0 * lda;
    const float* Bp = B + n0;

    float acc[NMT][NNT][4];
    #pragma unroll
    for (int i = 0; i < NMT; i++)
        #pragma unroll
        for (int j = 0; j < NNT; j++)
            #pragma unroll
            for (int e = 0; e < 4; e++) acc[i][j][e] = 0.f;

    float4 rA[NA4], rB[NB4];

    auto gload = [&](int k0) {
        #pragma unroll
        for (int e = 0; e < NA4; e++) {
            int f = tid + e * NT;
            rA[e] = *reinterpret_cast<const float4*>(
                Ap + (size_t)(f >> 2) * lda + k0 + (f & 3) * 4);
        }
        #pragma unroll
        for (int e = 0; e < NB4; e++) {
            int f = tid + e * NT;
            rB[e] = *reinterpret_cast<const float4*>(
                Bp + (size_t)(k0 + f / (BN / 4)) * ldb + (f % (BN / 4)) * 4);
        }
    };

    auto sstore = [&](int s) {
        __half* Ah = sh + s * STG;
        __half* Al = Ah + ASZ;
        __half* Bh = Ah + 2 * ASZ;
        __half* Bl = Ah + 2 * ASZ + BSZ;
        #pragma unroll
        for (int e = 0; e < NA4; e++) {
            int f = tid + e * NT; int m = f >> 2; int kq = (f & 3) * 4;
            float vv[4] = {rA[e].x, rA[e].y, rA[e].z, rA[e].w};
            __half hh[4], ll[4];
            #pragma unroll
            for (int i = 0; i < 4; i++) h_split(vv[i], hh[i], ll[i]);
            uint2 ph, pl;
            ph.x = pack2(hh[0], hh[1]); ph.y = pack2(hh[2], hh[3]);
            pl.x = pack2(ll[0], ll[1]); pl.y = pack2(ll[2], ll[3]);
            *reinterpret_cast<uint2*>(Ah + m * AKP + kq) = ph;
            *reinterpret_cast<uint2*>(Al + m * AKP + kq) = pl;
        }
        #pragma unroll
        for (int e = 0; e < NB4; e++) {
            int f = tid + e * NT; int kk = f / (BN / 4); int nq = (f % (BN / 4)) * 4;
            float vv[4] = {rB[e].x, rB[e].y, rB[e].z, rB[e].w};
            __half hh[4], ll[4];
            #pragma unroll
            for (int i = 0; i < 4; i++) h_split(vv[i], hh[i], ll[i]);
            uint2 ph, pl;
            ph.x = pack2(hh[0], hh[1]); ph.y = pack2(hh[2], hh[3]);
            pl.x = pack2(ll[0], ll[1]); pl.y = pack2(ll[2], ll[3]);
            *reinterpret_cast<uint2*>(Bh + kk * BNP + nq) = ph;
            *reinterpret_cast<uint2*>(Bl + kk * BNP + nq) = pl;
        }
    };

    gload(0);
    sstore(0);
    __syncthreads();

    const int ntiles = K >> 4;
    for (int kt = 0; kt < ntiles; kt++) {
        const bool more = (kt + 1 < ntiles);
        if (more) gload((kt + 1) << 4);

        const int s = kt & 1;
        const uint32_t sb = shb + (uint32_t)s * STG * 2;   // stage byte base
        const uint32_t abh = sb;
        const uint32_t abl = sb + ASZ * 2;
        const uint32_t bbh = sb + 4 * ASZ;                 // 2*ASZ halfs * 2B
        const uint32_t bbl = sb + 4 * ASZ + BSZ * 2;

        uint32_t ah[NMT][4], al[NMT][4];
        #pragma unroll
        for (int mt = 0; mt < NMT; mt++) {
            uint32_t aoff = (uint32_t)((wm + mt * 16 + (mi & 1) * 8 + mr) * AKP
                                       + (mi >> 1) * 8) * 2;
            ldsm4(ah[mt][0], ah[mt][1], ah[mt][2], ah[mt][3], abh + aoff);
            ldsm4(al[mt][0], al[mt][1], al[mt][2], al[mt][3], abl + aoff);
        }

        #pragma unroll
        for (int np = 0; np < NNT / 2; np++) {
            uint32_t off = (uint32_t)(lk * BNP + wn + np * 16 + lncol) * 2;
            uint32_t b0, b1, b2, b3, c0, c1, c2, c3;
            ldsm4t(b0, b1, b2, b3, bbh + off);
            ldsm4t(c0, c1, c2, c3, bbl + off);
            #pragma unroll
            for (int mt = 0; mt < NMT; mt++) {
                mma_f16a(acc[mt][2 * np],     ah[mt], b0, b1);
                mma_f16a(acc[mt][2 * np],     al[mt], b0, b1);
                mma_f16a(acc[mt][2 * np],     ah[mt], c0, c1);
                mma_f16a(acc[mt][2 * np + 1], ah[mt], b2, b3);
                mma_f16a(acc[mt][2 * np + 1], al[mt], b2, b3);
                mma_f16a(acc[mt][2 * np + 1], ah[mt], c2, c3);
            }
        }
        if (more) {
            sstore(1 - s);
            __syncthreads();
        }
    }

    // Epilogue
    #pragma unroll
    for (int mt = 0; mt < NMT; mt++) {
        int r0 = m0 + wm + mt * 16 + g;
        #pragma unroll
        for (int nt = 0; nt < NNT; nt++) {
            int cc = n0 + wn + nt * 8 + t * 2;
            float2 p0 = make_float2(acc[mt][nt][0], acc[mt][nt][1]);
            float2 p1 = make_float2(acc[mt][nt][2], acc[mt][nt][3]);
            float b0 = bias[cc], b1 = bias[cc + 1];
            p0.x += b0; p0.y += b1; p1.x += b0; p1.y += b1;
            if (EPI == 1) {
                p0.x = gelu_tanh(p0.x); p0.y = gelu_tanh(p0.y);
                p1.x = gelu_tanh(p1.x); p1.y = gelu_tanh(p1.y);
            }
            if (EPI == 2) {
                p0.x += R[(size_t)r0 * ldr + cc];
                p0.y += R[(size_t)r0 * ldr + cc + 1];
                p1.x += R[(size_t)(r0 + 8) * ldr + cc];
                p1.y += R[(size_t)(r0 + 8) * ldr + cc + 1];
            }
            *reinterpret_cast<float2*>(&C[(size_t)r0 * ldc + cc]) = p0;
            *reinterpret_cast<float2*>(&C[(size_t)(r0 + 8) * ldc + cc]) = p1;
        }
    }
}

// QKV fused via blockIdx.z — 512 threads
__global__ __launch_bounds__(512, 1)
void qkv_kernel(const float* __restrict__ h,
                const float* __restrict__ wq, const float* __restrict__ wk,
                const float* __restrict__ wv,
                const float* __restrict__ bq, const float* __restrict__ bk,
                const float* __restrict__ bv,
                float* __restrict__ q, float* __restrict__ k, float* __restrict__ v)
{
    int z = blockIdx.z;
    const float* W  = (z == 0) ? wq : (z == 1) ? wk : wv;
    const float* bi = (z == 0) ? bq : (z == 1) ? bk : bv;
    float* C        = (z == 0) ? q  : (z == 1) ? k  : v;
    gemm_core<512,128,128,32,32,0>(h, DD, W, DD, bi, nullptr, 0, C, DD,
                                   DD, blockIdx.y * 128, blockIdx.x * 128);
}

// FFN1 — 512 threads
__global__ __launch_bounds__(512, 1)
void ffn1_kernel(const float* __restrict__ A,
                 const float* __restrict__ B,
                 const float* __restrict__ bias,
                 float* __restrict__ C)
{
    gemm_core<512,128,128,32,32,1>(A, DD, B, FF, bias, nullptr, 0, C, FF,
                                   DD, blockIdx.y * 128, blockIdx.x * 128);
}

// O-proj / FFN2 — 256 threads, occ 2
template<int EPI>
__global__ __launch_bounds__(256, 2)
void mm_kernel(const float* __restrict__ A, int lda,
               const float* __restrict__ B, int ldb,
               const float* __restrict__ bias,
               const float* __restrict__ R, int ldr,
               float* __restrict__ C, int ldc, int K)
{
    gemm_core<256,64,128,32,32,EPI>(A, lda, B, ldb, bias, R, ldr, C, ldc,
                                    K, blockIdx.y * 64, blockIdx.x * 128);
}

// ---------------------------------------------------------------------------
// Fused flash attention + in-kernel rel bias. BJ=64 j-tiles (16 iters).
// K fragments via ldmatrix.x4; V via interleaved half2 scalar LDS. occ 3.
// (R10 configuration — fastest measured flash)
// ---------------------------------------------------------------------------
__global__ __launch_bounds__(128, 3)
void flash_kernel(const float* __restrict__ q, const float* __restrict__ k,
                  const float* __restrict__ v, const float* __restrict__ relw,
                  const int* __restrict__ rel_ids, const int* __restrict__ mask,
                  float* __restrict__ ctx)
{
    extern __shared__ float smf[];
    __half*  smh = reinterpret_cast<__half*>(smf);
    __half*  Qh = smh;                 // [64][72]
    __half*  Ql = smh + 4608;
    __half*  Kh = smh + 9216;          // [64][72]
    __half*  Kl = smh + 13824;
    __half2* Vh = reinterpret_cast<__half2*>(smh + 18432);  // [32 jp][72 d]
    float*   rels = reinterpret_cast<float*>(smh + 23040);  // [64][33] fp32
    __half*  Rwh = smh + 27264;        // [32][72]
    __half*  Rwl = smh + 29568;        // [32][72]

    const int tid  = threadIdx.x;
    const int lane = tid & 31;
    const int wid  = tid >> 5;
    const int g = lane >> 2, t = lane & 3;
    const int wm = wid << 4;
    const int mi = lane >> 3, mr = lane & 7;

    const int i0 = blockIdx.x * 64;
    const int bh = blockIdx.y;
    const int b = bh / HH, h = bh - b * HH;

    const float* Qp = q + (size_t)b * SS * DD + h * DHH;
    const float* Kp = k + (size_t)b * SS * DD + h * DHH;
    const float* Vp = v + (size_t)b * SS * DD + h * DHH;

    const uint32_t qhb = (uint32_t)__cvta_generic_to_shared(Qh);
    const uint32_t qlb = (uint32_t)__cvta_generic_to_shared(Ql);
    const uint32_t khb = (uint32_t)__cvta_generic_to_shared(Kh);
    const uint32_t klb = (uint32_t)__cvta_generic_to_shared(Kl);
    const uint32_t rhb = (uint32_t)__cvta_generic_to_shared(Rwh);
    const uint32_t rlb = (uint32_t)__cvta_generic_to_shared(Rwl);

    // Q tile -> Qh/Ql [row][d]
    {
        int row = tid & 63;
        int base = (tid >> 6) * 8;
        #pragma unroll
        for (int e = 0; e < 8; e++) {
            int dq = (base + e) * 4;
            float4 val = *reinterpret_cast<const float4*>(Qp + (size_t)(i0 + row) * DD + dq);
            float vv[4] = {val.x, val.y, val.z, val.w};
            __half hh[4], ll[4];
            #pragma unroll
            for (int i = 0; i < 4; i++) h_split(vv[i], hh[i], ll[i]);
            uint2 ph, pl;
            ph.x = pack2(hh[0], hh[1]); ph.y = pack2(hh[2], hh[3]);
            pl.x = pack2(ll[0], ll[1]); pl.y = pack2(ll[2], ll[3]);
            *reinterpret_cast<uint2*>(Qh + row * 72 + dq) = ph;
            *reinterpret_cast<uint2*>(Ql + row * 72 + dq) = pl;
        }
    }
    // rel_emb slice [RELV][DHH] for head h -> Rwh/Rwl
    {
        #pragma unroll
        for (int e = 0; e < 4; e++) {
            int f = tid + e * 128;
            int r = f >> 4, dq = (f & 15) * 4;
            float4 val = *reinterpret_cast<const float4*>(
                relw + ((size_t)r * HH + h) * DHH + dq);
            float vv[4] = {val.x, val.y, val.z, val.w};
            __half hh[4], ll[4];
            #pragma unroll
            for (int i = 0; i < 4; i++) h_split(vv[i], hh[i], ll[i]);
            uint2 ph, pl;
            ph.x = pack2(hh[0], hh[1]); ph.y = pack2(hh[2], hh[3]);
            pl.x = pack2(ll[0], ll[1]); pl.y = pack2(ll[2], ll[3]);
            *reinterpret_cast<uint2*>(Rwh + r * 72 + dq) = ph;
            *reinterpret_cast<uint2*>(Rwl + r * 72 + dq) = pl;
        }
    }
    __syncthreads();

    // Hoisted Q fragments via ldmatrix (4 k16 chunks)
    uint32_t qfh[4][4], qfl[4][4];
    {
        uint32_t qoff = (uint32_t)((wm + (mi & 1) * 8 + mr) * 72 + (mi >> 1) * 8) * 2;
        #pragma unroll
        for (int kc = 0; kc < 4; kc++) {
            ldsm4(qfh[kc][0], qfh[kc][1], qfh[kc][2], qfh[kc][3], qhb + qoff + kc * 32);
            ldsm4(qfl[kc][0], qfl[kc][1], qfl[kc][2], qfl[kc][3], qlb + qoff + kc * 32);
        }
    }

    // In-kernel rel bias: rel[i][r] = Q @ Rw^T (fp16x3) -> rels smem
    {
        float racc[4][4];
        #pragma unroll
        for (int nt = 0; nt < 4; nt++) {
            racc[nt][0] = 0.f; racc[nt][1] = 0.f; racc[nt][2] = 0.f; racc[nt][3] = 0.f;
        }
        uint32_t kfix = (uint32_t)(((mi >> 1) * 8 + mr) * 72 + (mi & 1) * 8) * 2;
        #pragma unroll
        for (int np = 0; np < 2; np++) {
            #pragma unroll
            for (int kc = 0; kc < 4; kc++) {
                uint32_t off = kfix + (uint32_t)(np * 16 * 72 + kc * 16) * 2;
                uint32_t b0, b1, b2, b3, c0, c1, c2, c3;
                ldsm4(b0, b1, b2, b3, rhb + off);
                ldsm4(c0, c1, c2, c3, rlb + off);
                mma_f16a(racc[2 * np],     qfh[kc], b0, b1);
                mma_f16a(racc[2 * np],     qfl[kc], b0, b1);
                mma_f16a(racc[2 * np],     qfh[kc], c0, c1);
                mma_f16a(racc[2 * np + 1], qfh[kc], b2, b3);
                mma_f16a(racc[2 * np + 1], qfl[kc], b2, b3);
                mma_f16a(racc[2 * np + 1], qfh[kc], c2, c3);
            }
        }
        int r0 = wm + g, r1 = r0 + 8;
        #pragma unroll
        for (int nt = 0; nt < 4; nt++) {
            rels[r0 * 33 + nt * 8 + 2 * t]     = racc[nt][0];
            rels[r0 * 33 + nt * 8 + 2 * t + 1] = racc[nt][1];
            rels[r1 * 33 + nt * 8 + 2 * t]     = racc[nt][2];
            rels[r1 * 33 + nt * 8 + 2 * t + 1] = racc[nt][3];
        }
        __syncwarp();
    }

    float m0r = -1e30f, m1r = -1e30f;
    float l0r = 0.f, l1r = 0.f;
    float oacc[8][4];
    #pragma unroll
    for (int nt = 0; nt < 8; nt++) {
        oacc[nt][0] = 0.f; oacc[nt][1] = 0.f; oacc[nt][2] = 0.f; oacc[nt][3] = 0.f;
    }

    const int ig0 = i0 + wm + g;
    const int ig1 = ig0 + 8;
    const int* rid0 = rel_ids + ((size_t)b * SS + ig0) * SS + 2 * t;
    const int* rid1 = rel_ids + ((size_t)b * SS + ig1) * SS + 2 * t;
    const int* mk0  = mask    + ((size_t)b * SS + ig0) * SS + 2 * t;
    const int* mk1  = mask    + ((size_t)b * SS + ig1) * SS + 2 * t;
    const float* rl0 = rels + (wm + g) * 33;
    const float* rl1 = rl0 + 8 * 33;

    const uint32_t kfix = (uint32_t)(((mi >> 1) * 8 + mr) * 72 + (mi & 1) * 8) * 2;

    for (int jt = 0; jt < 16; jt++) {
        const int j0 = jt * 64;
        __syncthreads();
        // K tile -> Kh/Kl [j][d], 64 rows
        {
            int row = tid >> 1;
            int base = (tid & 1) * 32;
            #pragma unroll
            for (int e = 0; e < 8; e++) {
                int dq = base + e * 4;
                float4 val = *reinterpret_cast<const float4*>(Kp + (size_t)(j0 + row) * DD + dq);
                float vv[4] = {val.x, val.y, val.z, val.w};
                __half hh[4], ll[4];
                #pragma unroll
                for (int i = 0; i < 4; i++) h_split(vv[i], hh[i], ll[i]);
                uint2 ph, pl;
                ph.x = pack2(hh[0], hh[1]); ph.y = pack2(hh[2], hh[3]);
                pl.x = pack2(ll[0], ll[1]); pl.y = pack2(ll[2], ll[3]);
                *reinterpret_cast<uint2*>(Kh + row * 72 + dq) = ph;
                *reinterpret_cast<uint2*>(Kl + row * 72 + dq) = pl;
            }
        }
        // V tile -> Vh[jpair][d] as half2(v_j, v_{j+1}), 32 pairs
        #pragma unroll
        for (int e = 0; e < 4; e++) {
            int f = tid + e * 128;
            int jp = f >> 4, dq = (f & 15) * 4;
            float4 v0 = *reinterpret_cast<const float4*>(Vp + (size_t)(j0 + 2 * jp) * DD + dq);
            float4 v1 = *reinterpret_cast<const float4*>(Vp + (size_t)(j0 + 2 * jp + 1) * DD + dq);
            __half2 d0 = __floats2half2_rn(v0.x, v1.x);
            __half2 d1 = __floats2half2_rn(v0.y, v1.y);
            __half2 d2 = __floats2half2_rn(v0.z, v1.z);
            __half2 d3 = __floats2half2_rn(v0.w, v1.w);
            uint4 pk;
            pk.x = *reinterpret_cast<uint32_t*>(&d0);
            pk.y = *reinterpret_cast<uint32_t*>(&d1);
            pk.z = *reinterpret_cast<uint32_t*>(&d2);
            pk.w = *reinterpret_cast<uint32_t*>(&d3);
            *reinterpret_cast<uint4*>(Vh + jp * 72 + dq) = pk;
        }
        __syncthreads();

        // S = Q K^T, 8 n8-tiles per warp, K frags via ldmatrix.x4
        float sacc[8][4];
        #pragma unroll
        for (int nt = 0; nt < 8; nt++) {
            sacc[nt][0] = 0.f; sacc[nt][1] = 0.f; sacc[nt][2] = 0.f; sacc[nt][3] = 0.f;
        }
        #pragma unroll
        for (int np = 0; np < 4; np++) {
            #pragma unroll
            for (int kc = 0; kc < 4; kc++) {
                uint32_t off = kfix + (uint32_t)(np * 16 * 72 + kc * 16) * 2;
                uint32_t b0, b1, b2, b3, c0, c1, c2, c3;
                ldsm4(b0, b1, b2, b3, khb + off);
                ldsm4(c0, c1, c2, c3, klb + off);
                mma_f16a(sacc[2 * np],     qfh[kc], b0, b1);
                mma_f16a(sacc[2 * np],     qfl[kc], b0, b1);
                mma_f16a(sacc[2 * np],     qfh[kc], c0, c1);
                mma_f16a(sacc[2 * np + 1], qfh[kc], b2, b3);
                mma_f16a(sacc[2 * np + 1], qfl[kc], b2, b3);
                mma_f16a(sacc[2 * np + 1], qfh[kc], c2, c3);
            }
        }

        // rel gather + mask + scale
        float mx0 = -1e30f, mx1 = -1e30f;
        #pragma unroll
        for (int nt = 0; nt < 8; nt++) {
            int jo = j0 + nt * 8;
            int2 i0v = *reinterpret_cast<const int2*>(rid0 + jo);
            int2 i1v = *reinterpret_cast<const int2*>(rid1 + jo);
            int2 m0v = *reinterpret_cast<const int2*>(mk0 + jo);
            int2 m1v = *reinterpret_cast<const int2*>(mk1 + jo);
            sacc[nt][0] = (sacc[nt][0] + rl0[i0v.x]) * 0.125f + (1.f - (float)m0v.x) * -10000.f;
            sacc[nt][1] = (sacc[nt][1] + rl0[i0v.y]) * 0.125f + (1.f - (float)m0v.y) * -10000.f;
            sacc[nt][2] = (sacc[nt][2] + rl1[i1v.x]) * 0.125f + (1.f - (float)m1v.x) * -10000.f;
            sacc[nt][3] = (sacc[nt][3] + rl1[i1v.y]) * 0.125f + (1.f - (float)m1v.y) * -10000.f;
            mx0 = fmaxf(mx0, fmaxf(sacc[nt][0], sacc[nt][1]));
            mx1 = fmaxf(mx1, fmaxf(sacc[nt][2], sacc[nt][3]));
        }
        mx0 = fmaxf(mx0, __shfl_xor_sync(0xffffffffu, mx0, 1));
        mx0 = fmaxf(mx0, __shfl_xor_sync(0xffffffffu, mx0, 2));
        mx1 = fmaxf(mx1, __shfl_xor_sync(0xffffffffu, mx1, 1));
        mx1 = fmaxf(mx1, __shfl_xor_sync(0xffffffffu, mx1, 2));
        float mn0 = fmaxf(m0r, mx0), mn1 = fmaxf(m1r, mx1);
        float al0 = __expf(m0r - mn0), al1 = __expf(m1r - mn1);
        m0r = mn0; m1r = mn1;

        // p = exp(s - m), pack to half2 (A-fragment layout = C-fragment layout)
        uint32_t ph[8][2];
        float s0 = 0.f, s1 = 0.f;
        #pragma unroll
        for (int nt = 0; nt < 8; nt++) {
            float p0 = __expf(sacc[nt][0] - mn0);
            float p1 = __expf(sacc[nt][1] - mn0);
            float p2 = __expf(sacc[nt][2] - mn1);
            float p3 = __expf(sacc[nt][3] - mn1);
            s0 += p0 + p1; s1 += p2 + p3;
            __half2 h01 = __floats2half2_rn(p0, p1);
            __half2 h23 = __floats2half2_rn(p2, p3);
            ph[nt][0] = *reinterpret_cast<uint32_t*>(&h01);
            ph[nt][1] = *reinterpret_cast<uint32_t*>(&h23);
        }
        l0r = l0r * al0 + s0;
        l1r = l1r * al1 + s1;
        #pragma unroll
        for (int nt = 0; nt < 8; nt++) {
            oacc[nt][0] *= al0; oacc[nt][1] *= al0;
            oacc[nt][2] *= al1; oacc[nt][3] *= al1;
        }
        // O += P @ V  (fp16, K=64 in 4 chunks of 16)
        #pragma unroll
        for (int kc = 0; kc < 4; kc++) {
            uint32_t a0 = ph[2 * kc][0],     a1 = ph[2 * kc][1];
            uint32_t a2 = ph[2 * kc + 1][0], a3 = ph[2 * kc + 1][1];
            #pragma unroll
            for (int nt = 0; nt < 8; nt++) {
                uint32_t b0 = *reinterpret_cast<const uint32_t*>(&Vh[(kc * 8 + t) * 72 + nt * 8 + g]);
                uint32_t b1 = *reinterpret_cast<const uint32_t*>(&Vh[(kc * 8 + t + 4) * 72 + nt * 8 + g]);
                mma_f16(oacc[nt], a0, a1, a2, a3, b0, b1);
            }
        }
    }

    // finalize
    l0r += __shfl_xor_sync(0xffffffffu, l0r, 1);
    l0r += __shfl_xor_sync(0xffffffffu, l0r, 2);
    l1r += __shfl_xor_sync(0xffffffffu, l1r, 1);
    l1r += __shfl_xor_sync(0xffffffffu, l1r, 2);
    float inv0 = 1.f / l0r, inv1 = 1.f / l1r;
    float* C0 = ctx + ((size_t)b * SS + ig0) * DD + h * DHH + 2 * t;
    float* C1 = ctx + ((size_t)b * SS + ig1) * DD + h * DHH + 2 * t;
    #pragma unroll
    for (int nt = 0; nt < 8; nt++) {
        *reinterpret_cast<float2*>(C0 + nt * 8) = make_float2(oacc[nt][0] * inv0, oacc[nt][1] * inv0);
        *reinterpret_cast<float2*>(C1 + nt * 8) = make_float2(oacc[nt][2] * inv1, oacc[nt][3] * inv1);
    }
}

// ---------------------------------------------------------------------------
// Block reduction (256 threads)
// ---------------------------------------------------------------------------
__device__ __forceinline__ float bsum256(float v) {
    __shared__ float sm[8];
    #pragma unroll
    for (int o = 16; o; o >>= 1) v += __shfl_xor_sync(0xffffffffu, v, o);
    if ((threadIdx.x & 31) == 0) sm[threadIdx.x >> 5] = v;
    __syncthreads();
    float r = 0.f;
    #pragma unroll
    for (int i = 0; i < 8; i++) r += sm[i];
    __syncthreads();
    return r;
}

// ---------------------------------------------------------------------------
// Embedding
// ---------------------------------------------------------------------------
__global__ void embed_kernel(const int* __restrict__ token_ids,
                             const int* __restrict__ segment_ids,
                             const int* __restrict__ position_ids,
                             const int* __restrict__ question_mask,
                             const float* __restrict__ tok_emb,
                             const float* __restrict__ seg_emb,
                             float* __restrict__ x)
{
    int row = blockIdx.x;
    int tok = token_ids[row];
    int seg = segment_ids[row];
    int qmi = question_mask[row];
    float qm = (float)qmi;
    int pos = position_ids[row] * qmi;
    float fpos = (float)pos;

    const float* te = tok_emb + (size_t)tok * DD;
    const float* se = seg_emb + (size_t)seg * DD;
    float* xr = x + (size_t)row * DD;

    for (int i = threadIdx.x; i < DD; i += 256) {
        float ex  = (float)(2 * (i >> 1)) * (1.0f / (float)DD);
        float inv = __powf(10000.0f, -ex);
        float ang = fpos * inv;
        float pe  = (i & 1) ? cosf(ang) : sinf(ang);
        xr[i] = te[i] + se[i] + pe * qm;
    }
}

// ---------------------------------------------------------------------------
// LayerNorm
// ---------------------------------------------------------------------------
__global__ void ln_kernel(const float* __restrict__ x,
                          const float* __restrict__ gamma,
                          const float* __restrict__ beta,
                          float* __restrict__ out)
{
    int row = blockIdx.x;
    const float* xr = x + (size_t)row * DD;
    int t = threadIdx.x;
    float v0 = xr[t], v1 = xr[t + 256], v2 = xr[t + 512];

    float s = bsum256(v0 + v1 + v2);
    float mu = s * (1.0f / (float)DD);
    float d0 = v0 - mu, d1 = v1 - mu, d2 = v2 - mu;
    float s2 = bsum256(d0*d0 + d1*d1 + d2*d2);
    float var = s2 * (1.0f / (float)DD);
    float rstd = rsqrtf(var + 1e-12f);

    float* orow = out + (size_t)row * DD;
    orow[t]       = d0 * rstd * gamma[t]       + beta[t];
    orow[t + 256] = d1 * rstd * gamma[t + 256] + beta[t + 256];
    orow[t + 512] = d2 * rstd * gamma[t + 512] + beta[t + 512];
}

// ---------------------------------------------------------------------------
// Launch
// ---------------------------------------------------------------------------
extern "C" void kernel_launch(void* const* d_in, const int* in_sizes, int n_in,
                              void* d_out, int out_size)
{
    const int* token_ids     = (const int*)d_in[0];
    const int* segment_ids   = (const int*)d_in[1];
    const int* position_ids  = (const int*)d_in[2];
    const int* question_mask = (const int*)d_in[3];
    const int* attention_mask= (const int*)d_in[4];
    const int* rel_ids       = (const int*)d_in[5];
    const float* tok_emb = (const float*)d_in[6];
    const float* seg_emb = (const float*)d_in[7];
    const float* ln1_g = (const float*)d_in[8];
    const float* ln1_b = (const float*)d_in[9];
    const float* ln2_g = (const float*)d_in[10];
    const float* ln2_b = (const float*)d_in[11];
    const float* wq = (const float*)d_in[12];
    const float* bq = (const float*)d_in[13];
    const float* wk = (const float*)d_in[14];
    const float* bk = (const float*)d_in[15];
    const float* wv = (const float*)d_in[16];
    const float* bv = (const float*)d_in[17];
    const float* wo = (const float*)d_in[18];
    const float* bo = (const float*)d_in[19];
    const float* rel_emb = (const float*)d_in[20];
    const float* w1 = (const float*)d_in[21];
    const float* b1 = (const float*)d_in[22];
    const float* w2 = (const float*)d_in[23];
    const float* b2 = (const float*)d_in[24];

    float *x, *h, *q, *k, *v, *ctx, *ff;
    cudaGetSymbolAddress((void**)&x,   g_x);
    cudaGetSymbolAddress((void**)&h,   g_h);
    cudaGetSymbolAddress((void**)&q,   g_q);
    cudaGetSymbolAddress((void**)&k,   g_k);
    cudaGetSymbolAddress((void**)&v,   g_v);
    cudaGetSymbolAddress((void**)&ctx, g_ctx);
    cudaGetSymbolAddress((void**)&ff,  g_ffn);

    const int FLASH_SMEM = 63744;
    cudaFuncSetAttribute(flash_kernel,
                         cudaFuncAttributeMaxDynamicSharedMemorySize, FLASH_SMEM);

    embed_kernel<<<NROW, 256>>>(token_ids, segment_ids, position_ids,
                                question_mask, tok_emb, seg_emb, x);

    for (int l = 0; l < LL; l++) {
        const float* wq_l = wq + (size_t)l * DD * DD;
        const float* wk_l = wk + (size_t)l * DD * DD;
        const float* wv_l = wv + (size_t)l * DD * DD;
        const float* wo_l = wo + (size_t)l * DD * DD;
        const float* w1_l = w1 + (size_t)l * DD * FF;
        const float* w2_l = w2 + (size_t)l * FF * DD;

        // --- attention block ---
        ln_kernel<<<NROW, 256>>>(x, ln1_g + l * DD, ln1_b + l * DD, h);

        qkv_kernel<<<dim3(DD / 128, NROW / 128, 3), 512>>>(
            h, wq_l, wk_l, wv_l, bq + l * DD, bk + l * DD, bv + l * DD, q, k, v);

        flash_kernel<<<dim3(SS / 64, BB * HH), 128, FLASH_SMEM>>>(
            q, k, v, rel_emb + (size_t)l * RELV * HH * DHH,
            rel_ids, attention_mask, ctx);

        // O-proj: BM=64, BN=128 -> grid (6,32)=192 CTAs, occ 2
        mm_kernel<2><<<dim3(DD / 128, NROW / 64), 256>>>(
            ctx, DD, wo_l, DD, bo + l * DD, x, DD, x, DD, DD);

        // --- FFN block ---
        ln_kernel<<<NROW, 256>>>(x, ln2_g + l * DD, ln2_b + l * DD, h);
        ffn1_kernel<<<dim3(FF / 128, NROW / 128), 512>>>(
            h, w1_l, b1 + l * FF, ff);

        float* outp = (l == LL - 1) ? (float*)d_out : x;
        // FFN2: BM=64, BN=128 -> grid (6,32)=192 CTAs, occ 2
        mm_kernel<2><<<dim3(DD / 128, NROW / 64), 256>>>(
            ff, FF, w2_l, DD, b2 + l * DD, x, DD, outp, DD, FF);
    }
}

// round 14
// speedup vs baseline: 1.0669x; 1.0122x over previous
#include <cuda_runtime.h>
#include <cuda_fp16.h>
#include <math.h>
#include <stdint.h>

// Problem constants
#define BB   2
#define SS   1024
#define DD   768
#define HH   12
#define DHH  64
#define LL   6
#define FF   3072
#define RELV 32
#define NROW (BB*SS)          // 2048 token rows

// ---------------------------------------------------------------------------
// Scratch (device globals; no dynamic allocation allowed)
// ---------------------------------------------------------------------------
__device__ float g_x  [NROW*DD];
__device__ float g_h  [NROW*DD];
__device__ float g_q  [NROW*DD];
__device__ float g_v  [NROW*DD];
__device__ float g_ctx[NROW*DD];
__device__ float g_ffn[(size_t)NROW*FF];
__device__ __align__(16) __half g_kh[NROW*DD];
__device__ __align__(16) __half g_kl[NROW*DD];

// ---------------------------------------------------------------------------
// fp16 helpers
// ---------------------------------------------------------------------------
__device__ __forceinline__ void h_split(float v, __half& hi, __half& lo) {
    hi = __float2half_rn(v);
    lo = __float2half_rn(v - __half2float(hi));
}

__device__ __forceinline__ uint32_t pack2(__half a, __half b) {
    __half2 t = __halves2half2(a, b);
    return *reinterpret_cast<uint32_t*>(&t);
}

__device__ __forceinline__ void mma_f16(float c[4], uint32_t a0, uint32_t a1,
                                        uint32_t a2, uint32_t a3,
                                        uint32_t b0, uint32_t b1) {
    asm volatile(
        "mma.sync.aligned.m16n8k16.row.col.f32.f16.f16.f32 "
        "{%0,%1,%2,%3},{%4,%5,%6,%7},{%8,%9},{%0,%1,%2,%3};"
        : "+f"(c[0]), "+f"(c[1]), "+f"(c[2]), "+f"(c[3])
        : "r"(a0), "r"(a1), "r"(a2), "r"(a3), "r"(b0), "r"(b1));
}

__device__ __forceinline__ void mma_f16a(float c[4], const uint32_t a[4],
                                         uint32_t b0, uint32_t b1) {
    mma_f16(c, a[0], a[1], a[2], a[3], b0, b1);
}

__device__ __forceinline__ void ldsm4(uint32_t& r0, uint32_t& r1,
                                      uint32_t& r2, uint32_t& r3, uint32_t a) {
    asm volatile("ldmatrix.sync.aligned.m8n8.x4.shared.b16 {%0,%1,%2,%3}, [%4];"
                 : "=r"(r0), "=r"(r1), "=r"(r2), "=r"(r3) : "r"(a));
}

__device__ __forceinline__ void ldsm4t(uint32_t& r0, uint32_t& r1,
                                       uint32_t& r2, uint32_t& r3, uint32_t a) {
    asm volatile("ldmatrix.sync.aligned.m8n8.x4.trans.shared.b16 {%0,%1,%2,%3}, [%4];"
                 : "=r"(r0), "=r"(r1), "=r"(r2), "=r"(r3) : "r"(a));
}

__device__ __forceinline__ float gelu_tanh(float v) {
    float u = 0.7978845608028654f * (v + 0.044715f * v * v * v);
    return 0.5f * v * (1.0f + tanhf(u));
}

// ---------------------------------------------------------------------------
// Tensor-core GEMM core: fp16x3 split, DOUBLE-BUFFERED smem (1 sync/k-tile).
// A fragments via ldmatrix.x4; B fragments via ldmatrix.x4.trans.
// EPI: 0=+bias, 1=+bias+gelu, 2=+bias+residual
// OUT: 0=fp32 C, 1=hi/lo half planes (Ch/Cl)
// ---------------------------------------------------------------------------
template<int NT, int BM, int BN, int WM, int WN, int EPI, int OUT>
__device__ __forceinline__ void gemm_core(
    const float* __restrict__ A, int lda,
    const float* __restrict__ B, int ldb,
    const float* __restrict__ bias,
    const float* __restrict__ R, int ldr,
    float* __restrict__ Cf, __half* __restrict__ Ch, __half* __restrict__ Cl,
    int ldc, int K, int m0, int n0)
{
    constexpr int NWN = BN / WN;
    constexpr int NMT = WM / 16;
    constexpr int NNT = WN / 8;
    constexpr int NA4 = (BM * 16) / (4 * NT);
    constexpr int NB4 = (BN * 16) / (4 * NT);
    constexpr int AKP = 24;
    constexpr int BNP = BN + 8;
    constexpr int ASZ = BM * AKP;
    constexpr int BSZ = 16 * BNP;
    constexpr int STG = 2 * ASZ + 2 * BSZ;

    __shared__ __align__(16) __half sh[2 * STG];

    const int tid  = threadIdx.x;
    const int lane = tid & 31;
    const int wid  = tid >> 5;
    const int g    = lane >> 2;
    const int t    = lane & 3;
    const int wm   = (wid / NWN) * WM;
    const int wn   = (wid % NWN) * WN;

    const int lk    = ((lane >> 3) & 1) * 8 + (lane & 7);
    const int lncol = ((lane >> 4) & 1) * 8;
    const int mi    = lane >> 3;
    const int mr    = lane & 7;
    const uint32_t shb = (uint32_t)__cvta_generic_to_shared(sh);

    const float* Ap = A + (size_t)m0 * lda;
    const float* Bp = B + n0;

    float acc[NMT][NNT][4];
    #pragma unroll
    for (int i = 0; i < NMT; i++)
        #pragma unroll
        for (int j = 0; j < NNT; j++)
            #pragma unroll
            for (int e = 0; e < 4; e++) acc[i][j][e] = 0.f;

    float4 rA[NA4], rB[NB4];

    auto gload = [&](int k0) {
        #pragma unroll
        for (int e = 0; e < NA4; e++) {
            int f = tid + e * NT;
            rA[e] = *reinterpret_cast<const float4*>(
                Ap + (size_t)(f >> 2) * lda + k0 + (f & 3) * 4);
        }
        #pragma unroll
        for (int e = 0; e < NB4; e++) {
            int f = tid + e * NT;
            rB[e] = *reinterpret_cast<const float4*>(
                Bp + (size_t)(k0 + f / (BN / 4)) * ldb + (f % (BN / 4)) * 4);
        }
    };

    auto sstore = [&](int s) {
        __half* Ah = sh + s * STG;
        __half* Al = Ah + ASZ;
        __half* Bh = Ah + 2 * ASZ;
        __half* Bl = Ah + 2 * ASZ + BSZ;
        #pragma unroll
        for (int e = 0; e < NA4; e++) {
            int f = tid + e * NT; int m = f >> 2; int kq = (f & 3) * 4;
            float vv[4] = {rA[e].x, rA[e].y, rA[e].z, rA[e].w};
            __half hh[4], ll[4];
            #pragma unroll
            for (int i = 0; i < 4; i++) h_split(vv[i], hh[i], ll[i]);
            uint2 ph, pl;
            ph.x = pack2(hh[0], hh[1]); ph.y = pack2(hh[2], hh[3]);
            pl.x = pack2(ll[0], ll[1]); pl.y = pack2(ll[2], ll[3]);
            *reinterpret_cast<uint2*>(Ah + m * AKP + kq) = ph;
            *reinterpret_cast<uint2*>(Al + m * AKP + kq) = pl;
        }
        #pragma unroll
        for (int e = 0; e < NB4; e++) {
            int f = tid + e * NT; int kk = f / (BN / 4); int nq = (f % (BN / 4)) * 4;
            float vv[4] = {rB[e].x, rB[e].y, rB[e].z, rB[e].w};
            __half hh[4], ll[4];
            #pragma unroll
            for (int i = 0; i < 4; i++) h_split(vv[i], hh[i], ll[i]);
            uint2 ph, pl;
            ph.x = pack2(hh[0], hh[1]); ph.y = pack2(hh[2], hh[3]);
            pl.x = pack2(ll[0], ll[1]); pl.y = pack2(ll[2], ll[3]);
            *reinterpret_cast<uint2*>(Bh + kk * BNP + nq) = ph;
            *reinterpret_cast<uint2*>(Bl + kk * BNP + nq) = pl;
        }
    };

    gload(0);
    sstore(0);
    __syncthreads();

    const int ntiles = K >> 4;
    for (int kt = 0; kt < ntiles; kt++) {
        const bool more = (kt + 1 < ntiles);
        if (more) gload((kt + 1) << 4);

        const int s = kt & 1;
        const uint32_t sb = shb + (uint32_t)s * STG * 2;
        const uint32_t abh = sb;
        const uint32_t abl = sb + ASZ * 2;
        const uint32_t bbh = sb + 4 * ASZ;
        const uint32_t bbl = sb + 4 * ASZ + BSZ * 2;

        uint32_t ah[NMT][4], al[NMT][4];
        #pragma unroll
        for (int mt = 0; mt < NMT; mt++) {
            uint32_t aoff = (uint32_t)((wm + mt * 16 + (mi & 1) * 8 + mr) * AKP
                                       + (mi >> 1) * 8) * 2;
            ldsm4(ah[mt][0], ah[mt][1], ah[mt][2], ah[mt][3], abh + aoff);
            ldsm4(al[mt][0], al[mt][1], al[mt][2], al[mt][3], abl + aoff);
        }

        #pragma unroll
        for (int np = 0; np < NNT / 2; np++) {
            uint32_t off = (uint32_t)(lk * BNP + wn + np * 16 + lncol) * 2;
            uint32_t b0, b1, b2, b3, c0, c1, c2, c3;
            ldsm4t(b0, b1, b2, b3, bbh + off);
            ldsm4t(c0, c1, c2, c3, bbl + off);
            #pragma unroll
            for (int mt = 0; mt < NMT; mt++) {
                mma_f16a(acc[mt][2 * np],     ah[mt], b0, b1);
                mma_f16a(acc[mt][2 * np],     al[mt], b0, b1);
                mma_f16a(acc[mt][2 * np],     ah[mt], c0, c1);
                mma_f16a(acc[mt][2 * np + 1], ah[mt], b2, b3);
                mma_f16a(acc[mt][2 * np + 1], al[mt], b2, b3);
                mma_f16a(acc[mt][2 * np + 1], ah[mt], c2, c3);
            }
        }
        if (more) {
            sstore(1 - s);
            __syncthreads();
        }
    }

    // Epilogue
    #pragma unroll
    for (int mt = 0; mt < NMT; mt++) {
        int r0 = m0 + wm + mt * 16 + g;
        #pragma unroll
        for (int nt = 0; nt < NNT; nt++) {
            int cc = n0 + wn + nt * 8 + t * 2;
            float v00 = acc[mt][nt][0], v01 = acc[mt][nt][1];
            float v10 = acc[mt][nt][2], v11 = acc[mt][nt][3];
            float b0 = bias[cc], b1 = bias[cc + 1];
            v00 += b0; v01 += b1; v10 += b0; v11 += b1;
            if (EPI == 1) {
                v00 = gelu_tanh(v00); v01 = gelu_tanh(v01);
                v10 = gelu_tanh(v10); v11 = gelu_tanh(v11);
            }
            if (EPI == 2) {
                v00 += R[(size_t)r0 * ldr + cc];
                v01 += R[(size_t)r0 * ldr + cc + 1];
                v10 += R[(size_t)(r0 + 8) * ldr + cc];
                v11 += R[(size_t)(r0 + 8) * ldr + cc + 1];
            }
            if (OUT == 0) {
                *reinterpret_cast<float2*>(&Cf[(size_t)r0 * ldc + cc]) = make_float2(v00, v01);
                *reinterpret_cast<float2*>(&Cf[(size_t)(r0 + 8) * ldc + cc]) = make_float2(v10, v11);
            } else {
                __half h0, h1, h2, h3, l0, l1, l2, l3;
                h_split(v00, h0, l0); h_split(v01, h1, l1);
                h_split(v10, h2, l2); h_split(v11, h3, l3);
                *reinterpret_cast<uint32_t*>(&Ch[(size_t)r0 * ldc + cc])       = pack2(h0, h1);
                *reinterpret_cast<uint32_t*>(&Cl[(size_t)r0 * ldc + cc])       = pack2(l0, l1);
                *reinterpret_cast<uint32_t*>(&Ch[(size_t)(r0 + 8) * ldc + cc]) = pack2(h2, h3);
                *reinterpret_cast<uint32_t*>(&Cl[(size_t)(r0 + 8) * ldc + cc]) = pack2(l2, l3);
            }
        }
    }
}

// QKV fused via blockIdx.z — 512 threads. z=1 (K) writes hi/lo half planes.
__global__ __launch_bounds__(512, 1)
void qkv_kernel(const float* __restrict__ h,
                const float* __restrict__ wq, const float* __restrict__ wk,
                const float* __restrict__ wv,
                const float* __restrict__ bq, const float* __restrict__ bk,
                const float* __restrict__ bv,
                float* __restrict__ q, __half* __restrict__ kh,
                __half* __restrict__ kl, float* __restrict__ v)
{
    int z = blockIdx.z;
    int m0 = blockIdx.y * 128, n0 = blockIdx.x * 128;
    if (z == 0)
        gemm_core<512,128,128,32,32,0,0>(h, DD, wq, DD, bq, nullptr, 0,
                                         q, nullptr, nullptr, DD, DD, m0, n0);
    else if (z == 1)
        gemm_core<512,128,128,32,32,0,1>(h, DD, wk, DD, bk, nullptr, 0,
                                         nullptr, kh, kl, DD, DD, m0, n0);
    else
        gemm_core<512,128,128,32,32,0,0>(h, DD, wv, DD, bv, nullptr, 0,
                                         v, nullptr, nullptr, DD, DD, m0, n0);
}

// FFN1 — 512 threads
__global__ __launch_bounds__(512, 1)
void ffn1_kernel(const float* __restrict__ A,
                 const float* __restrict__ B,
                 const float* __restrict__ bias,
                 float* __restrict__ C)
{
    gemm_core<512,128,128,32,32,1,0>(A, DD, B, FF, bias, nullptr, 0,
                                     C, nullptr, nullptr, FF, DD,
                                     blockIdx.y * 128, blockIdx.x * 128);
}

// O-proj / FFN2 — 256 threads, occ 2
template<int EPI>
__global__ __launch_bounds__(256, 2)
void mm_kernel(const float* __restrict__ A, int lda,
               const float* __restrict__ B, int ldb,
               const float* __restrict__ bias,
               const float* __restrict__ R, int ldr,
               float* __restrict__ C, int ldc, int K)
{
    gemm_core<256,64,128,32,32,EPI,0>(A, lda, B, ldb, bias, R, ldr,
                                      C, nullptr, nullptr, ldc, K,
                                      blockIdx.y * 64, blockIdx.x * 128);
}

// ---------------------------------------------------------------------------
// Fused flash attention + in-kernel rel bias. BJ=64 j-tiles (16 iters).
// K pre-split in gmem (hi/lo halves): fill = pure vector copy.
// K fragments via ldmatrix.x4; V via interleaved half2 scalar LDS. occ 3.
// ---------------------------------------------------------------------------
__global__ __launch_bounds__(128, 3)
void flash_kernel(const float* __restrict__ q,
                  const __half* __restrict__ kh, const __half* __restrict__ kl,
                  const float* __restrict__ v, const float* __restrict__ relw,
                  const int* __restrict__ rel_ids, const int* __restrict__ mask,
                  float* __restrict__ ctx)
{
    extern __shared__ float smf[];
    __half*  smh = reinterpret_cast<__half*>(smf);
    __half*  Qh = smh;                 // [64][72]
    __half*  Ql = smh + 4608;
    __half*  Kh = smh + 9216;          // [64][72]
    __half*  Kl = smh + 13824;
    __half2* Vh = reinterpret_cast<__half2*>(smh + 18432);  // [32 jp][72 d]
    float*   rels = reinterpret_cast<float*>(smh + 23040);  // [64][33] fp32
    __half*  Rwh = smh + 27264;        // [32][72]
    __half*  Rwl = smh + 29568;        // [32][72]

    const int tid  = threadIdx.x;
    const int lane = tid & 31;
    const int wid  = tid >> 5;
    const int g = lane >> 2, t = lane & 3;
    const int wm = wid << 4;
    const int mi = lane >> 3, mr = lane & 7;

    const int i0 = blockIdx.x * 64;
    const int bh = blockIdx.y;
    const int b = bh / HH, h = bh - b * HH;

    const float*  Qp  = q  + (size_t)b * SS * DD + h * DHH;
    const __half* Kph = kh + (size_t)b * SS * DD + h * DHH;
    const __half* Kpl = kl + (size_t)b * SS * DD + h * DHH;
    const float*  Vp  = v  + (size_t)b * SS * DD + h * DHH;

    const uint32_t qhb = (uint32_t)__cvta_generic_to_shared(Qh);
    const uint32_t qlb = (uint32_t)__cvta_generic_to_shared(Ql);
    const uint32_t khb = (uint32_t)__cvta_generic_to_shared(Kh);
    const uint32_t klb = (uint32_t)__cvta_generic_to_shared(Kl);
    const uint32_t rhb = (uint32_t)__cvta_generic_to_shared(Rwh);
    const uint32_t rlb = (uint32_t)__cvta_generic_to_shared(Rwl);

    // Q tile -> Qh/Ql [row][d]
    {
        int row = tid & 63;
        int base = (tid >> 6) * 8;
        #pragma unroll
        for (int e = 0; e < 8; e++) {
            int dq = (base + e) * 4;
            float4 val = *reinterpret_cast<const float4*>(Qp + (size_t)(i0 + row) * DD + dq);
            float vv[4] = {val.x, val.y, val.z, val.w};
            __half hh[4], ll[4];
            #pragma unroll
            for (int i = 0; i < 4; i++) h_split(vv[i], hh[i], ll[i]);
            uint2 ph, pl;
            ph.x = pack2(hh[0], hh[1]); ph.y = pack2(hh[2], hh[3]);
            pl.x = pack2(ll[0], ll[1]); pl.y = pack2(ll[2], ll[3]);
            *reinterpret_cast<uint2*>(Qh + row * 72 + dq) = ph;
            *reinterpret_cast<uint2*>(Ql + row * 72 + dq) = pl;
        }
    }
    // rel_emb slice [RELV][DHH] for head h -> Rwh/Rwl
    {
        #pragma unroll
        for (int e = 0; e < 4; e++) {
            int f = tid + e * 128;
            int r = f >> 4, dq = (f & 15) * 4;
            float4 val = *reinterpret_cast<const float4*>(
                relw + ((size_t)r * HH + h) * DHH + dq);
            float vv[4] = {val.x, val.y, val.z, val.w};
            __half hh[4], ll[4];
            #pragma unroll
            for (int i = 0; i < 4; i++) h_split(vv[i], hh[i], ll[i]);
            uint2 ph, pl;
            ph.x = pack2(hh[0], hh[1]); ph.y = pack2(hh[2], hh[3]);
            pl.x = pack2(ll[0], ll[1]); pl.y = pack2(ll[2], ll[3]);
            *reinterpret_cast<uint2*>(Rwh + r * 72 + dq) = ph;
            *reinterpret_cast<uint2*>(Rwl + r * 72 + dq) = pl;
        }
    }
    __syncthreads();

    // Hoisted Q fragments via ldmatrix (4 k16 chunks)
    uint32_t qfh[4][4], qfl[4][4];
    {
        uint32_t qoff = (uint32_t)((wm + (mi & 1) * 8 + mr) * 72 + (mi >> 1) * 8) * 2;
        #pragma unroll
        for (int kc = 0; kc < 4; kc++) {
            ldsm4(qfh[kc][0], qfh[kc][1], qfh[kc][2], qfh[kc][3], qhb + qoff + kc * 32);
            ldsm4(qfl[kc][0], qfl[kc][1], qfl[kc][2], qfl[kc][3], qlb + qoff + kc * 32);
        }
    }

    // In-kernel rel bias: rel[i][r] = Q @ Rw^T (fp16x3) -> rels smem
    {
        float racc[4][4];
        #pragma unroll
        for (int nt = 0; nt < 4; nt++) {
            racc[nt][0] = 0.f; racc[nt][1] = 0.f; racc[nt][2] = 0.f; racc[nt][3] = 0.f;
        }
        uint32_t kfix = (uint32_t)(((mi >> 1) * 8 + mr) * 72 + (mi & 1) * 8) * 2;
        #pragma unroll
        for (int np = 0; np < 2; np++) {
            #pragma unroll
            for (int kc = 0; kc < 4; kc++) {
                uint32_t off = kfix + (uint32_t)(np * 16 * 72 + kc * 16) * 2;
                uint32_t b0, b1, b2, b3, c0, c1, c2, c3;
                ldsm4(b0, b1, b2, b3, rhb + off);
                ldsm4(c0, c1, c2, c3, rlb + off);
                mma_f16a(racc[2 * np],     qfh[kc], b0, b1);
                mma_f16a(racc[2 * np],     qfl[kc], b0, b1);
                mma_f16a(racc[2 * np],     qfh[kc], c0, c1);
                mma_f16a(racc[2 * np + 1], qfh[kc], b2, b3);
                mma_f16a(racc[2 * np + 1], qfl[kc], b2, b3);
                mma_f16a(racc[2 * np + 1], qfh[kc], c2, c3);
            }
        }
        int r0 = wm + g, r1 = r0 + 8;
        #pragma unroll
        for (int nt = 0; nt < 4; nt++) {
            rels[r0 * 33 + nt * 8 + 2 * t]     = racc[nt][0];
            rels[r0 * 33 + nt * 8 + 2 * t + 1] = racc[nt][1];
            rels[r1 * 33 + nt * 8 + 2 * t]     = racc[nt][2];
            rels[r1 * 33 + nt * 8 + 2 * t + 1] = racc[nt][3];
        }
        __syncwarp();
    }

    float m0r = -1e30f, m1r = -1e30f;
    float l0r = 0.f, l1r = 0.f;
    float oacc[8][4];
    #pragma unroll
    for (int nt = 0; nt < 8; nt++) {
        oacc[nt][0] = 0.f; oacc[nt][1] = 0.f; oacc[nt][2] = 0.f; oacc[nt][3] = 0.f;
    }

    const int ig0 = i0 + wm + g;
    const int ig1 = ig0 + 8;
    const int* rid0 = rel_ids + ((size_t)b * SS + ig0) * SS + 2 * t;
    const int* rid1 = rel_ids + ((size_t)b * SS + ig1) * SS + 2 * t;
    const int* mk0  = mask    + ((size_t)b * SS + ig0) * SS + 2 * t;
    const int* mk1  = mask    + ((size_t)b * SS + ig1) * SS + 2 * t;
    const float* rl0 = rels + (wm + g) * 33;
    const float* rl1 = rl0 + 8 * 33;

    const uint32_t kfix = (uint32_t)(((mi >> 1) * 8 + mr) * 72 + (mi & 1) * 8) * 2;

    for (int jt = 0; jt < 16; jt++) {
        const int j0 = jt * 64;
        __syncthreads();
        // K tile -> Kh/Kl [j][d], 64 rows — pure vector copy (pre-split gmem)
        {
            int row = tid >> 1;
            int base = (tid & 1) * 32;
            const __half* srch = Kph + (size_t)(j0 + row) * DD + base;
            const __half* srcl = Kpl + (size_t)(j0 + row) * DD + base;
            __half* dsth = Kh + row * 72 + base;
            __half* dstl = Kl + row * 72 + base;
            #pragma unroll
            for (int e = 0; e < 4; e++) {
                *reinterpret_cast<uint4*>(dsth + e * 8) =
                    *reinterpret_cast<const uint4*>(srch + e * 8);
                *reinterpret_cast<uint4*>(dstl + e * 8) =
                    *reinterpret_cast<const uint4*>(srcl + e * 8);
            }
        }
        // V tile -> Vh[jpair][d] as half2(v_j, v_{j+1}), 32 pairs
        #pragma unroll
        for (int e = 0; e < 4; e++) {
            int f = tid + e * 128;
            int jp = f >> 4, dq = (f & 15) * 4;
            float4 v0 = *reinterpret_cast<const float4*>(Vp + (size_t)(j0 + 2 * jp) * DD + dq);
            float4 v1 = *reinterpret_cast<const float4*>(Vp + (size_t)(j0 + 2 * jp + 1) * DD + dq);
            __half2 d0 = __floats2half2_rn(v0.x, v1.x);
            __half2 d1 = __floats2half2_rn(v0.y, v1.y);
            __half2 d2 = __floats2half2_rn(v0.z, v1.z);
            __half2 d3 = __floats2half2_rn(v0.w, v1.w);
            uint4 pk;
            pk.x = *reinterpret_cast<uint32_t*>(&d0);
            pk.y = *reinterpret_cast<uint32_t*>(&d1);
            pk.z = *reinterpret_cast<uint32_t*>(&d2);
            pk.w = *reinterpret_cast<uint32_t*>(&d3);
            *reinterpret_cast<uint4*>(Vh + jp * 72 + dq) = pk;
        }
        __syncthreads();

        // S = Q K^T, 8 n8-tiles per warp, K frags via ldmatrix.x4
        float sacc[8][4];
        #pragma unroll
        for (int nt = 0; nt < 8; nt++) {
            sacc[nt][0] = 0.f; sacc[nt][1] = 0.f; sacc[nt][2] = 0.f; sacc[nt][3] = 0.f;
        }
        #pragma unroll
        for (int np = 0; np < 4; np++) {
            #pragma unroll
            for (int kc = 0; kc < 4; kc++) {
                uint32_t off = kfix + (uint32_t)(np * 16 * 72 + kc * 16) * 2;
                uint32_t b0, b1, b2, b3, c0, c1, c2, c3;
                ldsm4(b0, b1, b2, b3, khb + off);
                ldsm4(c0, c1, c2, c3, klb + off);
                mma_f16a(sacc[2 * np],     qfh[kc], b0, b1);
                mma_f16a(sacc[2 * np],     qfl[kc], b0, b1);
                mma_f16a(sacc[2 * np],     qfh[kc], c0, c1);
                mma_f16a(sacc[2 * np + 1], qfh[kc], b2, b3);
                mma_f16a(sacc[2 * np + 1], qfl[kc], b2, b3);
                mma_f16a(sacc[2 * np + 1], qfh[kc], c2, c3);
            }
        }

        // rel gather + mask + scale
        float mx0 = -1e30f, mx1 = -1e30f;
        #pragma unroll
        for (int nt = 0; nt < 8; nt++) {
            int jo = j0 + nt * 8;
            int2 i0v = *reinterpret_cast<const int2*>(rid0 + jo);
            int2 i1v = *reinterpret_cast<const int2*>(rid1 + jo);
            int2 m0v = *reinterpret_cast<const int2*>(mk0 + jo);
            int2 m1v = *reinterpret_cast<const int2*>(mk1 + jo);
            sacc[nt][0] = (sacc[nt][0] + rl0[i0v.x]) * 0.125f + (1.f - (float)m0v.x) * -10000.f;
            sacc[nt][1] = (sacc[nt][1] + rl0[i0v.y]) * 0.125f + (1.f - (float)m0v.y) * -10000.f;
            sacc[nt][2] = (sacc[nt][2] + rl1[i1v.x]) * 0.125f + (1.f - (float)m1v.x) * -10000.f;
            sacc[nt][3] = (sacc[nt][3] + rl1[i1v.y]) * 0.125f + (1.f - (float)m1v.y) * -10000.f;
            mx0 = fmaxf(mx0, fmaxf(sacc[nt][0], sacc[nt][1]));
            mx1 = fmaxf(mx1, fmaxf(sacc[nt][2], sacc[nt][3]));
        }
        mx0 = fmaxf(mx0, __shfl_xor_sync(0xffffffffu, mx0, 1));
        mx0 = fmaxf(mx0, __shfl_xor_sync(0xffffffffu, mx0, 2));
        mx1 = fmaxf(mx1, __shfl_xor_sync(0xffffffffu, mx1, 1));
        mx1 = fmaxf(mx1, __shfl_xor_sync(0xffffffffu, mx1, 2));
        float mn0 = fmaxf(m0r, mx0), mn1 = fmaxf(m1r, mx1);
        float al0 = __expf(m0r - mn0), al1 = __expf(m1r - mn1);
        m0r = mn0; m1r = mn1;

        // p = exp(s - m), pack to half2 (A-fragment layout = C-fragment layout)
        uint32_t ph[8][2];
        float s0 = 0.f, s1 = 0.f;
        #pragma unroll
        for (int nt = 0; nt < 8; nt++) {
            float p0 = __expf(sacc[nt][0] - mn0);
            float p1 = __expf(sacc[nt][1] - mn0);
            float p2 = __expf(sacc[nt][2] - mn1);
            float p3 = __expf(sacc[nt][3] - mn1);
            s0 += p0 + p1; s1 += p2 + p3;
            __half2 h01 = __floats2half2_rn(p0, p1);
            __half2 h23 = __floats2half2_rn(p2, p3);
            ph[nt][0] = *reinterpret_cast<uint32_t*>(&h01);
            ph[nt][1] = *reinterpret_cast<uint32_t*>(&h23);
        }
        l0r = l0r * al0 + s0;
        l1r = l1r * al1 + s1;
        #pragma unroll
        for (int nt = 0; nt < 8; nt++) {
            oacc[nt][0] *= al0; oacc[nt][1] *= al0;
            oacc[nt][2] *= al1; oacc[nt][3] *= al1;
        }
        // O += P @ V  (fp16, K=64 in 4 chunks of 16)
        #pragma unroll
        for (int kc = 0; kc < 4; kc++) {
            uint32_t a0 = ph[2 * kc][0],     a1 = ph[2 * kc][1];
            uint32_t a2 = ph[2 * kc + 1][0], a3 = ph[2 * kc + 1][1];
            #pragma unroll
            for (int nt = 0; nt < 8; nt++) {
                uint32_t b0 = *reinterpret_cast<const uint32_t*>(&Vh[(kc * 8 + t) * 72 + nt * 8 + g]);
                uint32_t b1 = *reinterpret_cast<const uint32_t*>(&Vh[(kc * 8 + t + 4) * 72 + nt * 8 + g]);
                mma_f16(oacc[nt], a0, a1, a2, a3, b0, b1);
            }
        }
    }

    // finalize
    l0r += __shfl_xor_sync(0xffffffffu, l0r, 1);
    l0r += __shfl_xor_sync(0xffffffffu, l0r, 2);
    l1r += __shfl_xor_sync(0xffffffffu, l1r, 1);
    l1r += __shfl_xor_sync(0xffffffffu, l1r, 2);
    float inv0 = 1.f / l0r, inv1 = 1.f / l1r;
    float* C0 = ctx + ((size_t)b * SS + ig0) * DD + h * DHH + 2 * t;
    float* C1 = ctx + ((size_t)b * SS + ig1) * DD + h * DHH + 2 * t;
    #pragma unroll
    for (int nt = 0; nt < 8; nt++) {
        *reinterpret_cast<float2*>(C0 + nt * 8) = make_float2(oacc[nt][0] * inv0, oacc[nt][1] * inv0);
        *reinterpret_cast<float2*>(C1 + nt * 8) = make_float2(oacc[nt][2] * inv1, oacc[nt][3] * inv1);
    }
}

// ---------------------------------------------------------------------------
// Block reduction (256 threads)
// ---------------------------------------------------------------------------
__device__ __forceinline__ float bsum256(float v) {
    __shared__ float sm[8];
    #pragma unroll
    for (int o = 16; o; o >>= 1) v += __shfl_xor_sync(0xffffffffu, v, o);
    if ((threadIdx.x & 31) == 0) sm[threadIdx.x >> 5] = v;
    __syncthreads();
    float r = 0.f;
    #pragma unroll
    for (int i = 0; i < 8; i++) r += sm[i];
    __syncthreads();
    return r;
}

// ---------------------------------------------------------------------------
// Embedding
// ---------------------------------------------------------------------------
__global__ void embed_kernel(const int* __restrict__ token_ids,
                             const int* __restrict__ segment_ids,
                             const int* __restrict__ position_ids,
                             const int* __restrict__ question_mask,
                             const float* __restrict__ tok_emb,
                             const float* __restrict__ seg_emb,
                             float* __restrict__ x)
{
    int row = blockIdx.x;
    int tok = token_ids[row];
    int seg = segment_ids[row];
    int qmi = question_mask[row];
    float qm = (float)qmi;
    int pos = position_ids[row] * qmi;
    float fpos = (float)pos;

    const float* te = tok_emb + (size_t)tok * DD;
    const float* se = seg_emb + (size_t)seg * DD;
    float* xr = x + (size_t)row * DD;

    for (int i = threadIdx.x; i < DD; i += 256) {
        float ex  = (float)(2 * (i >> 1)) * (1.0f / (float)DD);
        float inv = __powf(10000.0f, -ex);
        float ang = fpos * inv;
        float pe  = (i & 1) ? cosf(ang) : sinf(ang);
        xr[i] = te[i] + se[i] + pe * qm;
    }
}

// ---------------------------------------------------------------------------
// LayerNorm
// ---------------------------------------------------------------------------
__global__ void ln_kernel(const float* __restrict__ x,
                          const float* __restrict__ gamma,
                          const float* __restrict__ beta,
                          float* __restrict__ out)
{
    int row = blockIdx.x;
    const float* xr = x + (size_t)row * DD;
    int t = threadIdx.x;
    float v0 = xr[t], v1 = xr[t + 256], v2 = xr[t + 512];

    float s = bsum256(v0 + v1 + v2);
    float mu = s * (1.0f / (float)DD);
    float d0 = v0 - mu, d1 = v1 - mu, d2 = v2 - mu;
    float s2 = bsum256(d0*d0 + d1*d1 + d2*d2);
    float var = s2 * (1.0f / (float)DD);
    float rstd = rsqrtf(var + 1e-12f);

    float* orow = out + (size_t)row * DD;
    orow[t]       = d0 * rstd * gamma[t]       + beta[t];
    orow[t + 256] = d1 * rstd * gamma[t + 256] + beta[t + 256];
    orow[t + 512] = d2 * rstd * gamma[t + 512] + beta[t + 512];
}

// ---------------------------------------------------------------------------
// Launch
// ---------------------------------------------------------------------------
extern "C" void kernel_launch(void* const* d_in, const int* in_sizes, int n_in,
                              void* d_out, int out_size)
{
    const int* token_ids     = (const int*)d_in[0];
    const int* segment_ids   = (const int*)d_in[1];
    const int* position_ids  = (const int*)d_in[2];
    const int* question_mask = (const int*)d_in[3];
    const int* attention_mask= (const int*)d_in[4];
    const int* rel_ids       = (const int*)d_in[5];
    const float* tok_emb = (const float*)d_in[6];
    const float* seg_emb = (const float*)d_in[7];
    const float* ln1_g = (const float*)d_in[8];
    const float* ln1_b = (const float*)d_in[9];
    const float* ln2_g = (const float*)d_in[10];
    const float* ln2_b = (const float*)d_in[11];
    const float* wq = (const float*)d_in[12];
    const float* bq = (const float*)d_in[13];
    const float* wk = (const float*)d_in[14];
    const float* bk = (const float*)d_in[15];
    const float* wv = (const float*)d_in[16];
    const float* bv = (const float*)d_in[17];
    const float* wo = (const float*)d_in[18];
    const float* bo = (const float*)d_in[19];
    const float* rel_emb = (const float*)d_in[20];
    const float* w1 = (const float*)d_in[21];
    const float* b1 = (const float*)d_in[22];
    const float* w2 = (const float*)d_in[23];
    const float* b2 = (const float*)d_in[24];

    float *x, *h, *q, *v, *ctx, *ff;
    __half *kh, *kl;
    cudaGetSymbolAddress((void**)&x,   g_x);
    cudaGetSymbolAddress((void**)&h,   g_h);
    cudaGetSymbolAddress((void**)&q,   g_q);
    cudaGetSymbolAddress((void**)&v,   g_v);
    cudaGetSymbolAddress((void**)&ctx, g_ctx);
    cudaGetSymbolAddress((void**)&ff,  g_ffn);
    cudaGetSymbolAddress((void**)&kh,  g_kh);
    cudaGetSymbolAddress((void**)&kl,  g_kl);

    const int FLASH_SMEM = 63744;
    cudaFuncSetAttribute(flash_kernel,
                         cudaFuncAttributeMaxDynamicSharedMemorySize, FLASH_SMEM);

    embed_kernel<<<NROW, 256>>>(token_ids, segment_ids, position_ids,
                                question_mask, tok_emb, seg_emb, x);

    for (int l = 0; l < LL; l++) {
        const float* wq_l = wq + (size_t)l * DD * DD;
        const float* wk_l = wk + (size_t)l * DD * DD;
        const float* wv_l = wv + (size_t)l * DD * DD;
        const float* wo_l = wo + (size_t)l * DD * DD;
        const float* w1_l = w1 + (size_t)l * DD * FF;
        const float* w2_l = w2 + (size_t)l * FF * DD;

        // --- attention block ---
        ln_kernel<<<NROW, 256>>>(x, ln1_g + l * DD, ln1_b + l * DD, h);

        qkv_kernel<<<dim3(DD / 128, NROW / 128, 3), 512>>>(
            h, wq_l, wk_l, wv_l, bq + l * DD, bk + l * DD, bv + l * DD,
            q, kh, kl, v);

        flash_kernel<<<dim3(SS / 64, BB * HH), 128, FLASH_SMEM>>>(
            q, kh, kl, v, rel_emb + (size_t)l * RELV * HH * DHH,
            rel_ids, attention_mask, ctx);

        // O-proj: BM=64, BN=128 -> grid (6,32)=192 CTAs, occ 2
        mm_kernel<2><<<dim3(DD / 128, NROW / 64), 256>>>(
            ctx, DD, wo_l, DD, bo + l * DD, x, DD, x, DD, DD);

        // --- FFN block ---
        ln_kernel<<<NROW, 256>>>(x, ln2_g + l * DD, ln2_b + l * DD, h);
        ffn1_kernel<<<dim3(FF / 128, NROW / 128), 512>>>(
            h, w1_l, b1 + l * FF, ff);

        float* outp = (l == LL - 1) ? (float*)d_out : x;
        // FFN2: BM=64, BN=128 -> grid (6,32)=192 CTAs, occ 2
        mm_kernel<2><<<dim3(DD / 128, NROW / 64), 256>>>(
            ff, FF, w2_l, DD, b2 + l * DD, x, DD, outp, DD, FF);
    }
}

// round 15
// speedup vs baseline: 1.0772x; 1.0096x over previous
#include <cuda_runtime.h>
#include <cuda_fp16.h>
#include <math.h>
#include <stdint.h>

// Problem constants
#define BB   2
#define SS   1024
#define DD   768
#define HH   12
#define DHH  64
#define LL   6
#define FF   3072
#define RELV 32
#define NROW (BB*SS)          // 2048 token rows

// ---------------------------------------------------------------------------
// Scratch (device globals; no dynamic allocation allowed)
// ---------------------------------------------------------------------------
__device__ float g_x  [NROW*DD];
__device__ float g_h  [NROW*DD];
__device__ float g_q  [NROW*DD];
__device__ float g_v  [NROW*DD];
__device__ float g_ctx[NROW*DD];
__device__ float g_ffn[(size_t)NROW*FF];
__device__ __align__(16) __half g_kh[NROW*DD];
__device__ __align__(16) __half g_kl[NROW*DD];

// ---------------------------------------------------------------------------
// fp16 helpers
// ---------------------------------------------------------------------------
__device__ __forceinline__ void h_split(float v, __half& hi, __half& lo) {
    hi = __float2half_rn(v);
    lo = __float2half_rn(v - __half2float(hi));
}

__device__ __forceinline__ uint32_t pack2(__half a, __half b) {
    __half2 t = __halves2half2(a, b);
    return *reinterpret_cast<uint32_t*>(&t);
}

__device__ __forceinline__ void mma_f16(float c[4], uint32_t a0, uint32_t a1,
                                        uint32_t a2, uint32_t a3,
                                        uint32_t b0, uint32_t b1) {
    asm volatile(
        "mma.sync.aligned.m16n8k16.row.col.f32.f16.f16.f32 "
        "{%0,%1,%2,%3},{%4,%5,%6,%7},{%8,%9},{%0,%1,%2,%3};"
        : "+f"(c[0]), "+f"(c[1]), "+f"(c[2]), "+f"(c[3])
        : "r"(a0), "r"(a1), "r"(a2), "r"(a3), "r"(b0), "r"(b1));
}

__device__ __forceinline__ void mma_f16a(float c[4], const uint32_t a[4],
                                         uint32_t b0, uint32_t b1) {
    mma_f16(c, a[0], a[1], a[2], a[3], b0, b1);
}

__device__ __forceinline__ void ldsm4(uint32_t& r0, uint32_t& r1,
                                      uint32_t& r2, uint32_t& r3, uint32_t a) {
    asm volatile("ldmatrix.sync.aligned.m8n8.x4.shared.b16 {%0,%1,%2,%3}, [%4];"
                 : "=r"(r0), "=r"(r1), "=r"(r2), "=r"(r3) : "r"(a));
}

__device__ __forceinline__ void ldsm4t(uint32_t& r0, uint32_t& r1,
                                       uint32_t& r2, uint32_t& r3, uint32_t a) {
    asm volatile("ldmatrix.sync.aligned.m8n8.x4.trans.shared.b16 {%0,%1,%2,%3}, [%4];"
                 : "=r"(r0), "=r"(r1), "=r"(r2), "=r"(r3) : "r"(a));
}

__device__ __forceinline__ float gelu_tanh(float v) {
    float u = 0.7978845608028654f * (v + 0.044715f * v * v * v);
    return 0.5f * v * (1.0f + tanhf(u));
}

// ---------------------------------------------------------------------------
// Tensor-core GEMM core: fp16x3 split, DOUBLE-BUFFERED smem (1 sync/k-tile).
// A fragments via ldmatrix.x4; B fragments via ldmatrix.x4.trans.
// EPI: 0=+bias, 1=+bias+gelu, 2=+bias+residual
// OUT: 0=fp32 C, 1=hi/lo half planes (Ch/Cl)
// ---------------------------------------------------------------------------
template<int NT, int BM, int BN, int WM, int WN, int EPI, int OUT>
__device__ __forceinline__ void gemm_core(
    const float* __restrict__ A, int lda,
    const float* __restrict__ B, int ldb,
    const float* __restrict__ bias,
    const float* __restrict__ R, int ldr,
    float* __restrict__ Cf, __half* __restrict__ Ch, __half* __restrict__ Cl,
    int ldc, int K, int m0, int n0)
{
    constexpr int NWN = BN / WN;
    constexpr int NMT = WM / 16;
    constexpr int NNT = WN / 8;
    constexpr int NA4 = (BM * 16) / (4 * NT);
    constexpr int NB4 = (BN * 16) / (4 * NT);
    constexpr int AKP = 24;
    constexpr int BNP = BN + 8;
    constexpr int ASZ = BM * AKP;
    constexpr int BSZ = 16 * BNP;
    constexpr int STG = 2 * ASZ + 2 * BSZ;

    __shared__ __align__(16) __half sh[2 * STG];

    const int tid  = threadIdx.x;
    const int lane = tid & 31;
    const int wid  = tid >> 5;
    const int g    = lane >> 2;
    const int t    = lane & 3;
    const int wm   = (wid / NWN) * WM;
    const int wn   = (wid % NWN) * WN;

    const int lk    = ((lane >> 3) & 1) * 8 + (lane & 7);
    const int lncol = ((lane >> 4) & 1) * 8;
    const int mi    = lane >> 3;
    const int mr    = lane & 7;
    const uint32_t shb = (uint32_t)__cvta_generic_to_shared(sh);

    const float* Ap = A + (size_t)m0 * lda;
    const float* Bp = B + n0;

    float acc[NMT][NNT][4];
    #pragma unroll
    for (int i = 0; i < NMT; i++)
        #pragma unroll
        for (int j = 0; j < NNT; j++)
            #pragma unroll
            for (int e = 0; e < 4; e++) acc[i][j][e] = 0.f;

    float4 rA[NA4], rB[NB4];

    auto gload = [&](int k0) {
        #pragma unroll
        for (int e = 0; e < NA4; e++) {
            int f = tid + e * NT;
            rA[e] = *reinterpret_cast<const float4*>(
                Ap + (size_t)(f >> 2) * lda + k0 + (f & 3) * 4);
        }
        #pragma unroll
        for (int e = 0; e < NB4; e++) {
            int f = tid + e * NT;
            rB[e] = *reinterpret_cast<const float4*>(
                Bp + (size_t)(k0 + f / (BN / 4)) * ldb + (f % (BN / 4)) * 4);
        }
    };

    auto sstore = [&](int s) {
        __half* Ah = sh + s * STG;
        __half* Al = Ah + ASZ;
        __half* Bh = Ah + 2 * ASZ;
        __half* Bl = Ah + 2 * ASZ + BSZ;
        #pragma unroll
        for (int e = 0; e < NA4; e++) {
            int f = tid + e * NT; int m = f >> 2; int kq = (f & 3) * 4;
            float vv[4] = {rA[e].x, rA[e].y, rA[e].z, rA[e].w};
            __half hh[4], ll[4];
            #pragma unroll
            for (int i = 0; i < 4; i++) h_split(vv[i], hh[i], ll[i]);
            uint2 ph, pl;
            ph.x = pack2(hh[0], hh[1]); ph.y = pack2(hh[2], hh[3]);
            pl.x = pack2(ll[0], ll[1]); pl.y = pack2(ll[2], ll[3]);
            *reinterpret_cast<uint2*>(Ah + m * AKP + kq) = ph;
            *reinterpret_cast<uint2*>(Al + m * AKP + kq) = pl;
        }
        #pragma unroll
        for (int e = 0; e < NB4; e++) {
            int f = tid + e * NT; int kk = f / (BN / 4); int nq = (f % (BN / 4)) * 4;
            float vv[4] = {rB[e].x, rB[e].y, rB[e].z, rB[e].w};
            __half hh[4], ll[4];
            #pragma unroll
            for (int i = 0; i < 4; i++) h_split(vv[i], hh[i], ll[i]);
            uint2 ph, pl;
            ph.x = pack2(hh[0], hh[1]); ph.y = pack2(hh[2], hh[3]);
            pl.x = pack2(ll[0], ll[1]); pl.y = pack2(ll[2], ll[3]);
            *reinterpret_cast<uint2*>(Bh + kk * BNP + nq) = ph;
            *reinterpret_cast<uint2*>(Bl + kk * BNP + nq) = pl;
        }
    };

    gload(0);
    sstore(0);
    __syncthreads();

    const int ntiles = K >> 4;
    for (int kt = 0; kt < ntiles; kt++) {
        const bool more = (kt + 1 < ntiles);
        if (more) gload((kt + 1) << 4);

        const int s = kt & 1;
        const uint32_t sb = shb + (uint32_t)s * STG * 2;
        const uint32_t abh = sb;
        const uint32_t abl = sb + ASZ * 2;
        const uint32_t bbh = sb + 4 * ASZ;
        const uint32_t bbl = sb + 4 * ASZ + BSZ * 2;

        uint32_t ah[NMT][4], al[NMT][4];
        #pragma unroll
        for (int mt = 0; mt < NMT; mt++) {
            uint32_t aoff = (uint32_t)((wm + mt * 16 + (mi & 1) * 8 + mr) * AKP
                                       + (mi >> 1) * 8) * 2;
            ldsm4(ah[mt][0], ah[mt][1], ah[mt][2], ah[mt][3], abh + aoff);
            ldsm4(al[mt][0], al[mt][1], al[mt][2], al[mt][3], abl + aoff);
        }

        #pragma unroll
        for (int np = 0; np < NNT / 2; np++) {
            uint32_t off = (uint32_t)(lk * BNP + wn + np * 16 + lncol) * 2;
            uint32_t b0, b1, b2, b3, c0, c1, c2, c3;
            ldsm4t(b0, b1, b2, b3, bbh + off);
            ldsm4t(c0, c1, c2, c3, bbl + off);
            #pragma unroll
            for (int mt = 0; mt < NMT; mt++) {
                mma_f16a(acc[mt][2 * np],     ah[mt], b0, b1);
                mma_f16a(acc[mt][2 * np],     al[mt], b0, b1);
                mma_f16a(acc[mt][2 * np],     ah[mt], c0, c1);
                mma_f16a(acc[mt][2 * np + 1], ah[mt], b2, b3);
                mma_f16a(acc[mt][2 * np + 1], al[mt], b2, b3);
                mma_f16a(acc[mt][2 * np + 1], ah[mt], c2, c3);
            }
        }
        if (more) {
            sstore(1 - s);
            __syncthreads();
        }
    }

    // Epilogue
    #pragma unroll
    for (int mt = 0; mt < NMT; mt++) {
        int r0 = m0 + wm + mt * 16 + g;
        #pragma unroll
        for (int nt = 0; nt < NNT; nt++) {
            int cc = n0 + wn + nt * 8 + t * 2;
            float v00 = acc[mt][nt][0], v01 = acc[mt][nt][1];
            float v10 = acc[mt][nt][2], v11 = acc[mt][nt][3];
            float b0 = bias[cc], b1 = bias[cc + 1];
            v00 += b0; v01 += b1; v10 += b0; v11 += b1;
            if (EPI == 1) {
                v00 = gelu_tanh(v00); v01 = gelu_tanh(v01);
                v10 = gelu_tanh(v10); v11 = gelu_tanh(v11);
            }
            if (EPI == 2) {
                v00 += R[(size_t)r0 * ldr + cc];
                v01 += R[(size_t)r0 * ldr + cc + 1];
                v10 += R[(size_t)(r0 + 8) * ldr + cc];
                v11 += R[(size_t)(r0 + 8) * ldr + cc + 1];
            }
            if (OUT == 0) {
                *reinterpret_cast<float2*>(&Cf[(size_t)r0 * ldc + cc]) = make_float2(v00, v01);
                *reinterpret_cast<float2*>(&Cf[(size_t)(r0 + 8) * ldc + cc]) = make_float2(v10, v11);
            } else {
                __half h0, h1, h2, h3, l0, l1, l2, l3;
                h_split(v00, h0, l0); h_split(v01, h1, l1);
                h_split(v10, h2, l2); h_split(v11, h3, l3);
                *reinterpret_cast<uint32_t*>(&Ch[(size_t)r0 * ldc + cc])       = pack2(h0, h1);
                *reinterpret_cast<uint32_t*>(&Cl[(size_t)r0 * ldc + cc])       = pack2(l0, l1);
                *reinterpret_cast<uint32_t*>(&Ch[(size_t)(r0 + 8) * ldc + cc]) = pack2(h2, h3);
                *reinterpret_cast<uint32_t*>(&Cl[(size_t)(r0 + 8) * ldc + cc]) = pack2(l2, l3);
            }
        }
    }
}

// QKV fused via blockIdx.z — 512 threads. z=1 (K) writes hi/lo half planes.
__global__ __launch_bounds__(512, 1)
void qkv_kernel(const float* __restrict__ h,
                const float* __restrict__ wq, const float* __restrict__ wk,
                const float* __restrict__ wv,
                const float* __restrict__ bq, const float* __restrict__ bk,
                const float* __restrict__ bv,
                float* __restrict__ q, __half* __restrict__ kh,
                __half* __restrict__ kl, float* __restrict__ v)
{
    int z = blockIdx.z;
    int m0 = blockIdx.y * 128, n0 = blockIdx.x * 128;
    if (z == 0)
        gemm_core<512,128,128,32,32,0,0>(h, DD, wq, DD, bq, nullptr, 0,
                                         q, nullptr, nullptr, DD, DD, m0, n0);
    else if (z == 1)
        gemm_core<512,128,128,32,32,0,1>(h, DD, wk, DD, bk, nullptr, 0,
                                         nullptr, kh, kl, DD, DD, m0, n0);
    else
        gemm_core<512,128,128,32,32,0,0>(h, DD, wv, DD, bv, nullptr, 0,
                                         v, nullptr, nullptr, DD, DD, m0, n0);
}

// FFN1 — 512 threads
__global__ __launch_bounds__(512, 1)
void ffn1_kernel(const float* __restrict__ A,
                 const float* __restrict__ B,
                 const float* __restrict__ bias,
                 float* __restrict__ C)
{
    gemm_core<512,128,128,32,32,1,0>(A, DD, B, FF, bias, nullptr, 0,
                                     C, nullptr, nullptr, FF, DD,
                                     blockIdx.y * 128, blockIdx.x * 128);
}

// O-proj / FFN2 — 256 threads, occ 2
template<int EPI>
__global__ __launch_bounds__(256, 2)
void mm_kernel(const float* __restrict__ A, int lda,
               const float* __restrict__ B, int ldb,
               const float* __restrict__ bias,
               const float* __restrict__ R, int ldr,
               float* __restrict__ C, int ldc, int K)
{
    gemm_core<256,64,128,32,32,EPI,0>(A, lda, B, ldb, bias, R, ldr,
                                      C, nullptr, nullptr, ldc, K,
                                      blockIdx.y * 64, blockIdx.x * 128);
}

// ---------------------------------------------------------------------------
// Fused flash attention + in-kernel rel bias. BJ=64 j-tiles (16 iters).
// K pre-split in gmem (hi/lo halves): fill = pure vector copy.
// K fragments via ldmatrix.x4; V via interleaved half2 scalar LDS. occ 3.
// ---------------------------------------------------------------------------
__global__ __launch_bounds__(128, 3)
void flash_kernel(const float* __restrict__ q,
                  const __half* __restrict__ kh, const __half* __restrict__ kl,
                  const float* __restrict__ v, const float* __restrict__ relw,
                  const int* __restrict__ rel_ids, const int* __restrict__ mask,
                  float* __restrict__ ctx)
{
    extern __shared__ float smf[];
    __half*  smh = reinterpret_cast<__half*>(smf);
    __half*  Qh = smh;                 // [64][72]
    __half*  Ql = smh + 4608;
    __half*  Kh = smh + 9216;          // [64][72]
    __half*  Kl = smh + 13824;
    __half2* Vh = reinterpret_cast<__half2*>(smh + 18432);  // [32 jp][72 d]
    float*   rels = reinterpret_cast<float*>(smh + 23040);  // [64][33] fp32
    __half*  Rwh = smh + 27264;        // [32][72]
    __half*  Rwl = smh + 29568;        // [32][72]

    const int tid  = threadIdx.x;
    const int lane = tid & 31;
    const int wid  = tid >> 5;
    const int g = lane >> 2, t = lane & 3;
    const int wm = wid << 4;
    const int mi = lane >> 3, mr = lane & 7;

    const int i0 = blockIdx.x * 64;
    const int bh = blockIdx.y;
    const int b = bh / HH, h = bh - b * HH;

    const float*  Qp  = q  + (size_t)b * SS * DD + h * DHH;
    const __half* Kph = kh + (size_t)b * SS * DD + h * DHH;
    const __half* Kpl = kl + (size_t)b * SS * DD + h * DHH;
    const float*  Vp  = v  + (size_t)b * SS * DD + h * DHH;

    const uint32_t qhb = (uint32_t)__cvta_generic_to_shared(Qh);
    const uint32_t qlb = (uint32_t)__cvta_generic_to_shared(Ql);
    const uint32_t khb = (uint32_t)__cvta_generic_to_shared(Kh);
    const uint32_t klb = (uint32_t)__cvta_generic_to_shared(Kl);
    const uint32_t rhb = (uint32_t)__cvta_generic_to_shared(Rwh);
    const uint32_t rlb = (uint32_t)__cvta_generic_to_shared(Rwl);

    // Q tile -> Qh/Ql [row][d]
    {
        int row = tid & 63;
        int base = (tid >> 6) * 8;
        #pragma unroll
        for (int e = 0; e < 8; e++) {
            int dq = (base + e) * 4;
            float4 val = *reinterpret_cast<const float4*>(Qp + (size_t)(i0 + row) * DD + dq);
            float vv[4] = {val.x, val.y, val.z, val.w};
            __half hh[4], ll[4];
            #pragma unroll
            for (int i = 0; i < 4; i++) h_split(vv[i], hh[i], ll[i]);
            uint2 ph, pl;
            ph.x = pack2(hh[0], hh[1]); ph.y = pack2(hh[2], hh[3]);
            pl.x = pack2(ll[0], ll[1]); pl.y = pack2(ll[2], ll[3]);
            *reinterpret_cast<uint2*>(Qh + row * 72 + dq) = ph;
            *reinterpret_cast<uint2*>(Ql + row * 72 + dq) = pl;
        }
    }
    // rel_emb slice [RELV][DHH] for head h -> Rwh/Rwl
    {
        #pragma unroll
        for (int e = 0; e < 4; e++) {
            int f = tid + e * 128;
            int r = f >> 4, dq = (f & 15) * 4;
            float4 val = *reinterpret_cast<const float4*>(
                relw + ((size_t)r * HH + h) * DHH + dq);
            float vv[4] = {val.x, val.y, val.z, val.w};
            __half hh[4], ll[4];
            #pragma unroll
            for (int i = 0; i < 4; i++) h_split(vv[i], hh[i], ll[i]);
            uint2 ph, pl;
            ph.x = pack2(hh[0], hh[1]); ph.y = pack2(hh[2], hh[3]);
            pl.x = pack2(ll[0], ll[1]); pl.y = pack2(ll[2], ll[3]);
            *reinterpret_cast<uint2*>(Rwh + r * 72 + dq) = ph;
            *reinterpret_cast<uint2*>(Rwl + r * 72 + dq) = pl;
        }
    }
    __syncthreads();

    // Hoisted Q fragments via ldmatrix (4 k16 chunks)
    uint32_t qfh[4][4], qfl[4][4];
    {
        uint32_t qoff = (uint32_t)((wm + (mi & 1) * 8 + mr) * 72 + (mi >> 1) * 8) * 2;
        #pragma unroll
        for (int kc = 0; kc < 4; kc++) {
            ldsm4(qfh[kc][0], qfh[kc][1], qfh[kc][2], qfh[kc][3], qhb + qoff + kc * 32);
            ldsm4(qfl[kc][0], qfl[kc][1], qfl[kc][2], qfl[kc][3], qlb + qoff + kc * 32);
        }
    }

    // In-kernel rel bias: rel[i][r] = Q @ Rw^T (fp16x3) -> rels smem
    {
        float racc[4][4];
        #pragma unroll
        for (int nt = 0; nt < 4; nt++) {
            racc[nt][0] = 0.f; racc[nt][1] = 0.f; racc[nt][2] = 0.f; racc[nt][3] = 0.f;
        }
        uint32_t kfix = (uint32_t)(((mi >> 1) * 8 + mr) * 72 + (mi & 1) * 8) * 2;
        #pragma unroll
        for (int np = 0; np < 2; np++) {
            #pragma unroll
            for (int kc = 0; kc < 4; kc++) {
                uint32_t off = kfix + (uint32_t)(np * 16 * 72 + kc * 16) * 2;
                uint32_t b0, b1, b2, b3, c0, c1, c2, c3;
                ldsm4(b0, b1, b2, b3, rhb + off);
                ldsm4(c0, c1, c2, c3, rlb + off);
                mma_f16a(racc[2 * np],     qfh[kc], b0, b1);
                mma_f16a(racc[2 * np],     qfl[kc], b0, b1);
                mma_f16a(racc[2 * np],     qfh[kc], c0, c1);
                mma_f16a(racc[2 * np + 1], qfh[kc], b2, b3);
                mma_f16a(racc[2 * np + 1], qfl[kc], b2, b3);
                mma_f16a(racc[2 * np + 1], qfh[kc], c2, c3);
            }
        }
        int r0 = wm + g, r1 = r0 + 8;
        #pragma unroll
        for (int nt = 0; nt < 4; nt++) {
            rels[r0 * 33 + nt * 8 + 2 * t]     = racc[nt][0];
            rels[r0 * 33 + nt * 8 + 2 * t + 1] = racc[nt][1];
            rels[r1 * 33 + nt * 8 + 2 * t]     = racc[nt][2];
            rels[r1 * 33 + nt * 8 + 2 * t + 1] = racc[nt][3];
        }
        __syncwarp();
    }

    float m0r = -1e30f, m1r = -1e30f;
    float l0r = 0.f, l1r = 0.f;
    float oacc[8][4];
    #pragma unroll
    for (int nt = 0; nt < 8; nt++) {
        oacc[nt][0] = 0.f; oacc[nt][1] = 0.f; oacc[nt][2] = 0.f; oacc[nt][3] = 0.f;
    }

    const int ig0 = i0 + wm + g;
    const int ig1 = ig0 + 8;
    const int* rid0 = rel_ids + ((size_t)b * SS + ig0) * SS + 2 * t;
    const int* rid1 = rel_ids + ((size_t)b * SS + ig1) * SS + 2 * t;
    const int* mk0  = mask    + ((size_t)b * SS + ig0) * SS + 2 * t;
    const int* mk1  = mask    + ((size_t)b * SS + ig1) * SS + 2 * t;
    const float* rl0 = rels + (wm + g) * 33;
    const float* rl1 = rl0 + 8 * 33;

    const uint32_t kfix = (uint32_t)(((mi >> 1) * 8 + mr) * 72 + (mi & 1) * 8) * 2;

    for (int jt = 0; jt < 16; jt++) {
        const int j0 = jt * 64;
        __syncthreads();
        // K tile -> Kh/Kl [j][d], 64 rows — pure vector copy (pre-split gmem)
        {
            int row = tid >> 1;
            int base = (tid & 1) * 32;
            const __half* srch = Kph + (size_t)(j0 + row) * DD + base;
            const __half* srcl = Kpl + (size_t)(j0 + row) * DD + base;
            __half* dsth = Kh + row * 72 + base;
            __half* dstl = Kl + row * 72 + base;
            #pragma unroll
            for (int e = 0; e < 4; e++) {
                *reinterpret_cast<uint4*>(dsth + e * 8) =
                    *reinterpret_cast<const uint4*>(srch + e * 8);
                *reinterpret_cast<uint4*>(dstl + e * 8) =
                    *reinterpret_cast<const uint4*>(srcl + e * 8);
            }
        }
        // V tile -> Vh[jpair][d] as half2(v_j, v_{j+1}), 32 pairs
        #pragma unroll
        for (int e = 0; e < 4; e++) {
            int f = tid + e * 128;
            int jp = f >> 4, dq = (f & 15) * 4;
            float4 v0 = *reinterpret_cast<const float4*>(Vp + (size_t)(j0 + 2 * jp) * DD + dq);
            float4 v1 = *reinterpret_cast<const float4*>(Vp + (size_t)(j0 + 2 * jp + 1) * DD + dq);
            __half2 d0 = __floats2half2_rn(v0.x, v1.x);
            __half2 d1 = __floats2half2_rn(v0.y, v1.y);
            __half2 d2 = __floats2half2_rn(v0.z, v1.z);
            __half2 d3 = __floats2half2_rn(v0.w, v1.w);
            uint4 pk;
            pk.x = *reinterpret_cast<uint32_t*>(&d0);
            pk.y = *reinterpret_cast<uint32_t*>(&d1);
            pk.z = *reinterpret_cast<uint32_t*>(&d2);
            pk.w = *reinterpret_cast<uint32_t*>(&d3);
            *reinterpret_cast<uint4*>(Vh + jp * 72 + dq) = pk;
        }
        __syncthreads();

        // S = Q K^T, 8 n8-tiles per warp, K frags via ldmatrix.x4
        float sacc[8][4];
        #pragma unroll
        for (int nt = 0; nt < 8; nt++) {
            sacc[nt][0] = 0.f; sacc[nt][1] = 0.f; sacc[nt][2] = 0.f; sacc[nt][3] = 0.f;
        }
        #pragma unroll
        for (int np = 0; np < 4; np++) {
            #pragma unroll
            for (int kc = 0; kc < 4; kc++) {
                uint32_t off = kfix + (uint32_t)(np * 16 * 72 + kc * 16) * 2;
                uint32_t b0, b1, b2, b3, c0, c1, c2, c3;
                ldsm4(b0, b1, b2, b3, khb + off);
                ldsm4(c0, c1, c2, c3, klb + off);
                mma_f16a(sacc[2 * np],     qfh[kc], b0, b1);
                mma_f16a(sacc[2 * np],     qfl[kc], b0, b1);
                mma_f16a(sacc[2 * np],     qfh[kc], c0, c1);
                mma_f16a(sacc[2 * np + 1], qfh[kc], b2, b3);
                mma_f16a(sacc[2 * np + 1], qfl[kc], b2, b3);
                mma_f16a(sacc[2 * np + 1], qfh[kc], c2, c3);
            }
        }

        // rel gather + mask + scale
        float mx0 = -1e30f, mx1 = -1e30f;
        #pragma unroll
        for (int nt = 0; nt < 8; nt++) {
            int jo = j0 + nt * 8;
            int2 i0v = *reinterpret_cast<const int2*>(rid0 + jo);
            int2 i1v = *reinterpret_cast<const int2*>(rid1 + jo);
            int2 m0v = *reinterpret_cast<const int2*>(mk0 + jo);
            int2 m1v = *reinterpret_cast<const int2*>(mk1 + jo);
            sacc[nt][0] = (sacc[nt][0] + rl0[i0v.x]) * 0.125f + (1.f - (float)m0v.x) * -10000.f;
            sacc[nt][1] = (sacc[nt][1] + rl0[i0v.y]) * 0.125f + (1.f - (float)m0v.y) * -10000.f;
            sacc[nt][2] = (sacc[nt][2] + rl1[i1v.x]) * 0.125f + (1.f - (float)m1v.x) * -10000.f;
            sacc[nt][3] = (sacc[nt][3] + rl1[i1v.y]) * 0.125f + (1.f - (float)m1v.y) * -10000.f;
            mx0 = fmaxf(mx0, fmaxf(sacc[nt][0], sacc[nt][1]));
            mx1 = fmaxf(mx1, fmaxf(sacc[nt][2], sacc[nt][3]));
        }
        mx0 = fmaxf(mx0, __shfl_xor_sync(0xffffffffu, mx0, 1));
        mx0 = fmaxf(mx0, __shfl_xor_sync(0xffffffffu, mx0, 2));
        mx1 = fmaxf(mx1, __shfl_xor_sync(0xffffffffu, mx1, 1));
        mx1 = fmaxf(mx1, __shfl_xor_sync(0xffffffffu, mx1, 2));
        float mn0 = fmaxf(m0r, mx0), mn1 = fmaxf(m1r, mx1);
        float al0 = __expf(m0r - mn0), al1 = __expf(m1r - mn1);
        m0r = mn0; m1r = mn1;

        // p = exp(s - m), pack to half2 (A-fragment layout = C-fragment layout)
        uint32_t ph[8][2];
        float s0 = 0.f, s1 = 0.f;
        #pragma unroll
        for (int nt = 0; nt < 8; nt++) {
            float p0 = __expf(sacc[nt][0] - mn0);
            float p1 = __expf(sacc[nt][1] - mn0);
            float p2 = __expf(sacc[nt][2] - mn1);
            float p3 = __expf(sacc[nt][3] - mn1);
            s0 += p0 + p1; s1 += p2 + p3;
            __half2 h01 = __floats2half2_rn(p0, p1);
            __half2 h23 = __floats2half2_rn(p2, p3);
            ph[nt][0] = *reinterpret_cast<uint32_t*>(&h01);
            ph[nt][1] = *reinterpret_cast<uint32_t*>(&h23);
        }
        l0r = l0r * al0 + s0;
        l1r = l1r * al1 + s1;
        #pragma unroll
        for (int nt = 0; nt < 8; nt++) {
            oacc[nt][0] *= al0; oacc[nt][1] *= al0;
            oacc[nt][2] *= al1; oacc[nt][3] *= al1;
        }
        // O += P @ V  (fp16, K=64 in 4 chunks of 16)
        #pragma unroll
        for (int kc = 0; kc < 4; kc++) {
            uint32_t a0 = ph[2 * kc][0],     a1 = ph[2 * kc][1];
            uint32_t a2 = ph[2 * kc + 1][0], a3 = ph[2 * kc + 1][1];
            #pragma unroll
            for (int nt = 0; nt < 8; nt++) {
                uint32_t b0 = *reinterpret_cast<const uint32_t*>(&Vh[(kc * 8 + t) * 72 + nt * 8 + g]);
                uint32_t b1 = *reinterpret_cast<const uint32_t*>(&Vh[(kc * 8 + t + 4) * 72 + nt * 8 + g]);
                mma_f16(oacc[nt], a0, a1, a2, a3, b0, b1);
            }
        }
    }

    // finalize
    l0r += __shfl_xor_sync(0xffffffffu, l0r, 1);
    l0r += __shfl_xor_sync(0xffffffffu, l0r, 2);
    l1r += __shfl_xor_sync(0xffffffffu, l1r, 1);
    l1r += __shfl_xor_sync(0xffffffffu, l1r, 2);
    float inv0 = 1.f / l0r, inv1 = 1.f / l1r;
    float* C0 = ctx + ((size_t)b * SS + ig0) * DD + h * DHH + 2 * t;
    float* C1 = ctx + ((size_t)b * SS + ig1) * DD + h * DHH + 2 * t;
    #pragma unroll
    for (int nt = 0; nt < 8; nt++) {
        *reinterpret_cast<float2*>(C0 + nt * 8) = make_float2(oacc[nt][0] * inv0, oacc[nt][1] * inv0);
        *reinterpret_cast<float2*>(C1 + nt * 8) = make_float2(oacc[nt][2] * inv1, oacc[nt][3] * inv1);
    }
}

// ---------------------------------------------------------------------------
// Block reduction (256 threads)
// ---------------------------------------------------------------------------
__device__ __forceinline__ float bsum256(float v) {
    __shared__ float sm[8];
    #pragma unroll
    for (int o = 16; o; o >>= 1) v += __shfl_xor_sync(0xffffffffu, v, o);
    if ((threadIdx.x & 31) == 0) sm[threadIdx.x >> 5] = v;
    __syncthreads();
    float r = 0.f;
    #pragma unroll
    for (int i = 0; i < 8; i++) r += sm[i];
    __syncthreads();
    return r;
}

// ---------------------------------------------------------------------------
// Embedding
// ---------------------------------------------------------------------------
__global__ void embed_kernel(const int* __restrict__ token_ids,
                             const int* __restrict__ segment_ids,
                             const int* __restrict__ position_ids,
                             const int* __restrict__ question_mask,
                             const float* __restrict__ tok_emb,
                             const float* __restrict__ seg_emb,
                             float* __restrict__ x)
{
    int row = blockIdx.x;
    int tok = token_ids[row];
    int seg = segment_ids[row];
    int qmi = question_mask[row];
    float qm = (float)qmi;
    int pos = position_ids[row] * qmi;
    float fpos = (float)pos;

    const float* te = tok_emb + (size_t)tok * DD;
    const float* se = seg_emb + (size_t)seg * DD;
    float* xr = x + (size_t)row * DD;

    for (int i = threadIdx.x; i < DD; i += 256) {
        float ex  = (float)(2 * (i >> 1)) * (1.0f / (float)DD);
        float inv = __powf(10000.0f, -ex);
        float ang = fpos * inv;
        float pe  = (i & 1) ? cosf(ang) : sinf(ang);
        xr[i] = te[i] + se[i] + pe * qm;
    }
}

// ---------------------------------------------------------------------------
// LayerNorm
// ---------------------------------------------------------------------------
__global__ void ln_kernel(const float* __restrict__ x,
                          const float* __restrict__ gamma,
                          const float* __restrict__ beta,
                          float* __restrict__ out)
{
    int row = blockIdx.x;
    const float* xr = x + (size_t)row * DD;
    int t = threadIdx.x;
    float v0 = xr[t], v1 = xr[t + 256], v2 = xr[t + 512];

    float s = bsum256(v0 + v1 + v2);
    float mu = s * (1.0f / (float)DD);
    float d0 = v0 - mu, d1 = v1 - mu, d2 = v2 - mu;
    float s2 = bsum256(d0*d0 + d1*d1 + d2*d2);
    float var = s2 * (1.0f / (float)DD);
    float rstd = rsqrtf(var + 1e-12f);

    float* orow = out + (size_t)row * DD;
    orow[t]       = d0 * rstd * gamma[t]       + beta[t];
    orow[t + 256] = d1 * rstd * gamma[t + 256] + beta[t + 256];
    orow[t + 512] = d2 * rstd * gamma[t + 512] + beta[t + 512];
}

// ---------------------------------------------------------------------------
// Launch
// ---------------------------------------------------------------------------
extern "C" void kernel_launch(void* const* d_in, const int* in_sizes, int n_in,
                              void* d_out, int out_size)
{
    const int* token_ids     = (const int*)d_in[0];
    const int* segment_ids   = (const int*)d_in[1];
    const int* position_ids  = (const int*)d_in[2];
    const int* question_mask = (const int*)d_in[3];
    const int* attention_mask= (const int*)d_in[4];
    const int* rel_ids       = (const int*)d_in[5];
    const float* tok_emb = (const float*)d_in[6];
    const float* seg_emb = (const float*)d_in[7];
    const float* ln1_g = (const float*)d_in[8];
    const float* ln1_b = (const float*)d_in[9];
    const float* ln2_g = (const float*)d_in[10];
    const float* ln2_b = (const float*)d_in[11];
    const float* wq = (const float*)d_in[12];
    const float* bq = (const float*)d_in[13];
    const float* wk = (const float*)d_in[14];
    const float* bk = (const float*)d_in[15];
    const float* wv = (const float*)d_in[16];
    const float* bv = (const float*)d_in[17];
    const float* wo = (const float*)d_in[18];
    const float* bo = (const float*)d_in[19];
    const float* rel_emb = (const float*)d_in[20];
    const float* w1 = (const float*)d_in[21];
    const float* b1 = (const float*)d_in[22];
    const float* w2 = (const float*)d_in[23];
    const float* b2 = (const float*)d_in[24];

    float *x, *h, *q, *v, *ctx, *ff;
    __half *kh, *kl;
    cudaGetSymbolAddress((void**)&x,   g_x);
    cudaGetSymbolAddress((void**)&h,   g_h);
    cudaGetSymbolAddress((void**)&q,   g_q);
    cudaGetSymbolAddress((void**)&v,   g_v);
    cudaGetSymbolAddress((void**)&ctx, g_ctx);
    cudaGetSymbolAddress((void**)&ff,  g_ffn);
    cudaGetSymbolAddress((void**)&kh,  g_kh);
    cudaGetSymbolAddress((void**)&kl,  g_kl);

    const int FLASH_SMEM = 63744;
    cudaFuncSetAttribute(flash_kernel,
                         cudaFuncAttributeMaxDynamicSharedMemorySize, FLASH_SMEM);

    embed_kernel<<<NROW, 256>>>(token_ids, segment_ids, position_ids,
                                question_mask, tok_emb, seg_emb, x);

    for (int l = 0; l < LL; l++) {
        const float* wq_l = wq + (size_t)l * DD * DD;
        const float* wk_l = wk + (size_t)l * DD * DD;
        const float* wv_l = wv + (size_t)l * DD * DD;
        const float* wo_l = wo + (size_t)l * DD * DD;
        const float* w1_l = w1 + (size_t)l * DD * FF;
        const float* w2_l = w2 + (size_t)l * FF * DD;

        // --- attention block ---
        ln_kernel<<<NROW, 256>>>(x, ln1_g + l * DD, ln1_b + l * DD, h);

        qkv_kernel<<<dim3(DD / 128, NROW / 128, 3), 512>>>(
            h, wq_l, wk_l, wv_l, bq + l * DD, bk + l * DD, bv + l * DD,
            q, kh, kl, v);

        flash_kernel<<<dim3(SS / 64, BB * HH), 128, FLASH_SMEM>>>(
            q, kh, kl, v, rel_emb + (size_t)l * RELV * HH * DHH,
            rel_ids, attention_mask, ctx);

        // O-proj: BM=64, BN=128 -> grid (6,32)=192 CTAs, occ 2
        mm_kernel<2><<<dim3(DD / 128, NROW / 64), 256>>>(
            ctx, DD, wo_l, DD, bo + l * DD, x, DD, x, DD, DD);

        // --- FFN block ---
        ln_kernel<<<NROW, 256>>>(x, ln2_g + l * DD, ln2_b + l * DD, h);
        ffn1_kernel<<<dim3(FF / 128, NROW / 128), 512>>>(
            h, w1_l, b1 + l * FF, ff);

        float* outp = (l == LL - 1) ? (float*)d_out : x;
        // FFN2: BM=64, BN=128 -> grid (6,32)=192 CTAs, occ 2
        mm_kernel<2><<<dim3(DD / 128, NROW / 64), 256>>>(
            ff, FF, w2_l, DD, b2 + l * DD, x, DD, outp, DD, FF);
    }
}